// round 1
// baseline (speedup 1.0000x reference)
#include <cuda_runtime.h>
#include <cuda_bf16.h>
#include <math.h>

// ---------------------------------------------------------------------------
// Problem constants
// ---------------------------------------------------------------------------
#define BB 8
#define SS 2048
#define MM 512
#define EE 1024
#define HH 16
#define DD 64

// ---------------------------------------------------------------------------
// Scratch (device globals; no allocation allowed)
// ---------------------------------------------------------------------------
__device__ float g_KV[MM * 2 * EE];          // K | V projections of memory (512 x 2048)
__device__ float g_Qp[BB * SS * EE];         // Q projection (prescaled by 1/8)
__device__ float g_attn[BB * SS * EE];       // attention output
__device__ float g_y[BB * SS * EE];          // out-proj + residual (pre-LN)
__device__ float g_wq[BB * EE];              // mean(query, axis=1)
__device__ float g_vw[BB * EE];              // wq @ Wv_w^T + bv_w
__device__ float g_upd[BB * EE];             // upd vector per batch
__device__ float g_gmem[MM * EE];            // memory @ G1^T + gate_b
__device__ float g_gupd[BB * EE];            // upd @ G2^T

// ---------------------------------------------------------------------------
// SGEMM (NT): C[M,N] = scale * (A[M,K] @ B[N,K]^T + bias[N]) + res[M,N]
// A row-major lda, B row-major ldb (K contiguous in both). M,N multiples of 128,
// K multiple of 16.
// ---------------------------------------------------------------------------
__global__ __launch_bounds__(256) void sgemm_nt(
    const float* __restrict__ A, int lda,
    const float* __restrict__ B, int ldb,
    const float* __restrict__ bias,
    const float* __restrict__ res,
    float* __restrict__ C, int M, int N, int K, float scale)
{
    __shared__ float As[16][128];
    __shared__ float Bs[16][128];

    const int tid = threadIdx.x;
    const int bn = blockIdx.x, bm = blockIdx.y;
    const int tx = tid & 15, ty = tid >> 4;
    const int lr = tid >> 2;            // 0..63
    const int lk = (tid & 3) * 4;       // 0,4,8,12

    const float* Ab = A + (size_t)(bm * 128) * lda;
    const float* Bb = B + (size_t)(bn * 128) * ldb;

    float acc[8][8];
#pragma unroll
    for (int i = 0; i < 8; i++)
#pragma unroll
        for (int j = 0; j < 8; j++) acc[i][j] = 0.f;

    for (int kt = 0; kt < K; kt += 16) {
        float4 a0 = *(const float4*)(Ab + (size_t)lr * lda + kt + lk);
        float4 a1 = *(const float4*)(Ab + (size_t)(lr + 64) * lda + kt + lk);
        float4 b0 = *(const float4*)(Bb + (size_t)lr * ldb + kt + lk);
        float4 b1 = *(const float4*)(Bb + (size_t)(lr + 64) * ldb + kt + lk);
        __syncthreads();
        As[lk + 0][lr] = a0.x; As[lk + 1][lr] = a0.y; As[lk + 2][lr] = a0.z; As[lk + 3][lr] = a0.w;
        As[lk + 0][lr + 64] = a1.x; As[lk + 1][lr + 64] = a1.y; As[lk + 2][lr + 64] = a1.z; As[lk + 3][lr + 64] = a1.w;
        Bs[lk + 0][lr] = b0.x; Bs[lk + 1][lr] = b0.y; Bs[lk + 2][lr] = b0.z; Bs[lk + 3][lr] = b0.w;
        Bs[lk + 0][lr + 64] = b1.x; Bs[lk + 1][lr + 64] = b1.y; Bs[lk + 2][lr + 64] = b1.z; Bs[lk + 3][lr + 64] = b1.w;
        __syncthreads();
#pragma unroll
        for (int kk = 0; kk < 16; kk++) {
            float4 af0 = *(float4*)&As[kk][ty * 4];
            float4 af1 = *(float4*)&As[kk][ty * 4 + 64];
            float4 bf0 = *(float4*)&Bs[kk][tx * 4];
            float4 bf1 = *(float4*)&Bs[kk][tx * 4 + 64];
            float a_[8] = {af0.x, af0.y, af0.z, af0.w, af1.x, af1.y, af1.z, af1.w};
            float b_[8] = {bf0.x, bf0.y, bf0.z, bf0.w, bf1.x, bf1.y, bf1.z, bf1.w};
#pragma unroll
            for (int i = 0; i < 8; i++)
#pragma unroll
                for (int j = 0; j < 8; j++)
                    acc[i][j] = fmaf(a_[i], b_[j], acc[i][j]);
        }
    }

#pragma unroll
    for (int i = 0; i < 8; i++) {
        int rr = (i < 4) ? (ty * 4 + i) : (64 + ty * 4 + (i - 4));
        size_t r = (size_t)bm * 128 + rr;
#pragma unroll
        for (int jh = 0; jh < 2; jh++) {
            int cc = tx * 4 + jh * 64;
            size_t cbase = (size_t)bn * 128 + cc;
            float4 bsv = make_float4(0.f, 0.f, 0.f, 0.f);
            if (bias) bsv = *(const float4*)(bias + cbase);
            float4 v;
            v.x = (acc[i][jh * 4 + 0] + bsv.x) * scale;
            v.y = (acc[i][jh * 4 + 1] + bsv.y) * scale;
            v.z = (acc[i][jh * 4 + 2] + bsv.z) * scale;
            v.w = (acc[i][jh * 4 + 3] + bsv.w) * scale;
            if (res) {
                float4 rv = *(const float4*)(res + r * N + cbase);
                v.x += rv.x; v.y += rv.y; v.z += rv.z; v.w += rv.w;
            }
            *(float4*)(C + r * N + cbase) = v;
        }
    }
}

// ---------------------------------------------------------------------------
// Flash-style attention. Qp prescaled by 1/sqrt(D). KV: (M, 2E), K cols h*64+d,
// V cols 1024+h*64+d. Grid: (S/32, H, B). 128 threads.
// ---------------------------------------------------------------------------
__global__ __launch_bounds__(128) void attn_kernel(
    const float* __restrict__ Qp,
    const float* __restrict__ KV,
    float* __restrict__ O)
{
    __shared__ float Qt[64][36];   // [d][q]
    __shared__ float Kt[64][68];   // [d][j]; overlaid by Ps[64][36] ([j][q])
    __shared__ float Vs[64][68];   // [j][d]

    const int b = blockIdx.z, h = blockIdx.y;
    const int s0 = blockIdx.x * 32;
    const int tid = threadIdx.x;
    const int tx = tid & 15, ty = tid >> 4;

    // Load Q tile (transposed)
    {
        int q = tid >> 2;
        int d0 = (tid & 3) * 16;
        const float* src = Qp + ((size_t)(b * SS + s0 + q)) * EE + h * DD + d0;
#pragma unroll
        for (int i = 0; i < 4; i++) {
            float4 v = *(const float4*)(src + i * 4);
            Qt[d0 + i * 4 + 0][q] = v.x; Qt[d0 + i * 4 + 1][q] = v.y;
            Qt[d0 + i * 4 + 2][q] = v.z; Qt[d0 + i * 4 + 3][q] = v.w;
        }
    }

    float o[4][4];
#pragma unroll
    for (int i = 0; i < 4; i++)
#pragma unroll
        for (int j = 0; j < 4; j++) o[i][j] = 0.f;
    float mrow[4] = {-1e30f, -1e30f, -1e30f, -1e30f};
    float lrow[4] = {0.f, 0.f, 0.f, 0.f};

    float* Ps = &Kt[0][0];

    for (int kc = 0; kc < MM / 64; kc++) {
        const int k0 = kc * 64;
        __syncthreads();   // protect Vs/Ps from previous iteration readers
        // Load K (transposed) and V
        {
            int j = tid >> 1;
            int d0 = (tid & 1) * 32;
            const float* ksrc = KV + (size_t)(k0 + j) * (2 * EE) + h * DD + d0;
            const float* vsrc = ksrc + EE;
#pragma unroll
            for (int i = 0; i < 8; i++) {
                float4 kv4 = *(const float4*)(ksrc + i * 4);
                Kt[d0 + i * 4 + 0][j] = kv4.x; Kt[d0 + i * 4 + 1][j] = kv4.y;
                Kt[d0 + i * 4 + 2][j] = kv4.z; Kt[d0 + i * 4 + 3][j] = kv4.w;
            }
#pragma unroll
            for (int i = 0; i < 8; i++)
                *(float4*)&Vs[j][d0 + i * 4] = *(const float4*)(vsrc + i * 4);
        }
        __syncthreads();

        // Scores: acc[qi][ji], q = ty*4+qi, j = tx*4+ji (already scaled via Qp)
        float acc[4][4];
#pragma unroll
        for (int i = 0; i < 4; i++)
#pragma unroll
            for (int j = 0; j < 4; j++) acc[i][j] = 0.f;
#pragma unroll 4
        for (int d = 0; d < 64; d++) {
            float4 qv = *(float4*)&Qt[d][ty * 4];
            float4 kv = *(float4*)&Kt[d][tx * 4];
            float qa[4] = {qv.x, qv.y, qv.z, qv.w};
            float ka[4] = {kv.x, kv.y, kv.z, kv.w};
#pragma unroll
            for (int qi = 0; qi < 4; qi++)
#pragma unroll
                for (int ji = 0; ji < 4; ji++)
                    acc[qi][ji] = fmaf(qa[qi], ka[ji], acc[qi][ji]);
        }

        // Online softmax (16 threads per q-row group share same ty; they occupy
        // a contiguous 16-lane half-warp, so xor-shuffles of 1..8 stay in-group)
#pragma unroll
        for (int qi = 0; qi < 4; qi++) {
            float tm = fmaxf(fmaxf(acc[qi][0], acc[qi][1]), fmaxf(acc[qi][2], acc[qi][3]));
#pragma unroll
            for (int off = 8; off >= 1; off >>= 1)
                tm = fmaxf(tm, __shfl_xor_sync(0xffffffffu, tm, off));
            float newm = fmaxf(mrow[qi], tm);
            float fac = __expf(mrow[qi] - newm);
            float ps = 0.f;
#pragma unroll
            for (int ji = 0; ji < 4; ji++) {
                acc[qi][ji] = __expf(acc[qi][ji] - newm);
                ps += acc[qi][ji];
            }
#pragma unroll
            for (int off = 8; off >= 1; off >>= 1)
                ps += __shfl_xor_sync(0xffffffffu, ps, off);
            lrow[qi] = lrow[qi] * fac + ps;
            mrow[qi] = newm;
#pragma unroll
            for (int di = 0; di < 4; di++) o[qi][di] *= fac;
        }
        __syncthreads();   // all done reading Kt before overlaying Ps

        // Write P transposed: Ps[j][q]
#pragma unroll
        for (int ji = 0; ji < 4; ji++)
#pragma unroll
            for (int qi = 0; qi < 4; qi++)
                Ps[(tx * 4 + ji) * 36 + ty * 4 + qi] = acc[qi][ji];
        __syncthreads();

        // O += P @ V : o[qi][di], d = tx*4+di
#pragma unroll 4
        for (int j = 0; j < 64; j++) {
            float4 pv = *(float4*)&Ps[j * 36 + ty * 4];
            float4 vv = *(float4*)&Vs[j][tx * 4];
            float pa[4] = {pv.x, pv.y, pv.z, pv.w};
            float va[4] = {vv.x, vv.y, vv.z, vv.w};
#pragma unroll
            for (int qi = 0; qi < 4; qi++)
#pragma unroll
                for (int di = 0; di < 4; di++)
                    o[qi][di] = fmaf(pa[qi], va[di], o[qi][di]);
        }
    }

#pragma unroll
    for (int qi = 0; qi < 4; qi++) {
        float inv = 1.f / lrow[qi];
        float4 v;
        v.x = o[qi][0] * inv; v.y = o[qi][1] * inv;
        v.z = o[qi][2] * inv; v.w = o[qi][3] * inv;
        *(float4*)&O[((size_t)(b * SS + s0 + ty * 4 + qi)) * EE + h * DD + tx * 4] = v;
    }
}

// ---------------------------------------------------------------------------
// Block reduction of (sum, sumsq) across 256 threads
// ---------------------------------------------------------------------------
__device__ __forceinline__ void block_reduce2(float& s1, float& s2) {
    __shared__ float r1[8], r2[8];
    int lane = threadIdx.x & 31, w = threadIdx.x >> 5;
#pragma unroll
    for (int off = 16; off; off >>= 1) {
        s1 += __shfl_xor_sync(0xffffffffu, s1, off);
        s2 += __shfl_xor_sync(0xffffffffu, s2, off);
    }
    if (lane == 0) { r1[w] = s1; r2[w] = s2; }
    __syncthreads();
    if (w == 0) {
        s1 = (lane < 8) ? r1[lane] : 0.f;
        s2 = (lane < 8) ? r2[lane] : 0.f;
#pragma unroll
        for (int off = 4; off; off >>= 1) {
            s1 += __shfl_xor_sync(0xffffffffu, s1, off);
            s2 += __shfl_xor_sync(0xffffffffu, s2, off);
        }
        if (lane == 0) { r1[0] = s1; r2[0] = s2; }
    }
    __syncthreads();
    s1 = r1[0]; s2 = r2[0];
}

// LayerNorm over rows of 1024 (256 threads/block, 1 block/row)
__global__ __launch_bounds__(256) void ln_kernel(
    const float* __restrict__ X, const float* __restrict__ g,
    const float* __restrict__ bta, float* __restrict__ out)
{
    size_t row = blockIdx.x;
    const float* x = X + row * EE;
    int c = threadIdx.x * 4;
    float4 v = *(const float4*)(x + c);
    float s1 = v.x + v.y + v.z + v.w;
    float s2 = v.x * v.x + v.y * v.y + v.z * v.z + v.w * v.w;
    block_reduce2(s1, s2);
    float mu = s1 * (1.f / EE);
    float var = s2 * (1.f / EE) - mu * mu;
    float rs = rsqrtf(var + 1e-5f);
    float4 gg = *(const float4*)(g + c);
    float4 bb = *(const float4*)(bta + c);
    float4 o;
    o.x = (v.x - mu) * rs * gg.x + bb.x;
    o.y = (v.y - mu) * rs * gg.y + bb.y;
    o.z = (v.z - mu) * rs * gg.z + bb.z;
    o.w = (v.w - mu) * rs * gg.w + bb.w;
    *(float4*)(out + row * EE + c) = o;
}

// new_mem: gate + blend + layernorm. Grid 4096 (= B*M), 256 threads.
__global__ __launch_bounds__(256) void newmem_kernel(
    const float* __restrict__ gmemM,   // (M,E) includes gate_b
    const float* __restrict__ gupd,    // (B,E)
    const float* __restrict__ upd,     // (B,E)
    const float* __restrict__ memv,    // (M,E)
    const float* __restrict__ wg, const float* __restrict__ wb,
    float* __restrict__ out)
{
    int row = blockIdx.x;
    int b = row >> 9, m = row & 511;
    int c = threadIdx.x * 4;
    float4 gm = *(const float4*)(gmemM + (size_t)m * EE + c);
    float4 gu = *(const float4*)(gupd + (size_t)b * EE + c);
    float4 uv = *(const float4*)(upd + (size_t)b * EE + c);
    float4 mv = *(const float4*)(memv + (size_t)m * EE + c);
    float ge[4] = {gm.x + gu.x, gm.y + gu.y, gm.z + gu.z, gm.w + gu.w};
    float u[4] = {uv.x, uv.y, uv.z, uv.w};
    float mmv[4] = {mv.x, mv.y, mv.z, mv.w};
    float x[4];
    float s1 = 0.f, s2 = 0.f;
#pragma unroll
    for (int i = 0; i < 4; i++) {
        float gt = 1.f / (1.f + __expf(-ge[i]));
        x[i] = gt * u[i] + (1.f - gt) * mmv[i];
        s1 += x[i]; s2 += x[i] * x[i];
    }
    block_reduce2(s1, s2);
    float mu = s1 * (1.f / EE);
    float var = s2 * (1.f / EE) - mu * mu;
    float rs = rsqrtf(var + 1e-5f);
    float4 gg = *(const float4*)(wg + c);
    float4 bb = *(const float4*)(wb + c);
    float4 o;
    o.x = (x[0] - mu) * rs * gg.x + bb.x;
    o.y = (x[1] - mu) * rs * gg.y + bb.y;
    o.z = (x[2] - mu) * rs * gg.z + bb.z;
    o.w = (x[3] - mu) * rs * gg.w + bb.w;
    *(float4*)(out + (size_t)row * EE + c) = o;
}

// wq = mean over S. Grid (E/32, B), 256 threads (8 s-strips x 32 e).
__global__ __launch_bounds__(256) void mean_kernel(
    const float* __restrict__ q, float* __restrict__ wq)
{
    __shared__ float red[8][33];
    int b = blockIdx.y;
    int e0 = blockIdx.x * 32;
    int el = threadIdx.x & 31, strip = threadIdx.x >> 5;
    const float* p = q + ((size_t)b * SS + strip * 256) * EE + e0 + el;
    float s = 0.f;
#pragma unroll 4
    for (int i = 0; i < 256; i++) s += p[(size_t)i * EE];
    red[strip][el] = s;
    __syncthreads();
    if (strip == 0) {
        float t = 0.f;
#pragma unroll
        for (int k = 0; k < 8; k++) t += red[k][el];
        wq[(size_t)b * EE + e0 + el] = t * (1.f / SS);
    }
}

// Tiny GEMV batch: C[8,N] = A[8,K] @ B^T (+bias). One warp per n.
__global__ __launch_bounds__(256) void gemv8(
    const float* __restrict__ A,
    const float* __restrict__ B, int ldb,
    const float* __restrict__ bias,
    float* __restrict__ C, int N, int K)
{
    int w = threadIdx.x >> 5, lane = threadIdx.x & 31;
    int n = blockIdx.x * 8 + w;
    if (n >= N) return;
    const float* brow = B + (size_t)n * ldb;
    for (int b = 0; b < BB; b++) {
        const float* arow = A + (size_t)b * K;
        float s = 0.f;
        for (int i = lane; i < K; i += 32) s += arow[i] * brow[i];
#pragma unroll
        for (int off = 16; off; off >>= 1) s += __shfl_xor_sync(0xffffffffu, s, off);
        if (lane == 0) C[(size_t)b * N + n] = s + (bias ? bias[n] : 0.f);
    }
}

// ---------------------------------------------------------------------------
extern "C" void kernel_launch(void* const* d_in, const int* in_sizes, int n_in,
                              void* d_out, int out_size)
{
    (void)in_sizes; (void)n_in; (void)out_size;
    const float* query   = (const float*)d_in[0];
    const float* memory  = (const float*)d_in[1];
    const float* r_in_w  = (const float*)d_in[2];
    const float* r_in_b  = (const float*)d_in[3];
    const float* r_out_w = (const float*)d_in[4];
    const float* r_out_b = (const float*)d_in[5];
    const float* w_in_w  = (const float*)d_in[6];
    const float* w_in_b  = (const float*)d_in[7];
    const float* w_out_w = (const float*)d_in[8];
    const float* w_out_b = (const float*)d_in[9];
    const float* rn_g    = (const float*)d_in[10];
    const float* rn_b    = (const float*)d_in[11];
    const float* wn_g    = (const float*)d_in[12];
    const float* wn_b    = (const float*)d_in[13];
    const float* gate_w  = (const float*)d_in[14];
    const float* gate_b  = (const float*)d_in[15];
    float* out = (float*)d_out;

    float *KV, *Qp, *attn, *y, *wq, *vw, *upd, *gmem, *gupd;
    cudaGetSymbolAddress((void**)&KV,   g_KV);
    cudaGetSymbolAddress((void**)&Qp,   g_Qp);
    cudaGetSymbolAddress((void**)&attn, g_attn);
    cudaGetSymbolAddress((void**)&y,    g_y);
    cudaGetSymbolAddress((void**)&wq,   g_wq);
    cudaGetSymbolAddress((void**)&vw,   g_vw);
    cudaGetSymbolAddress((void**)&upd,  g_upd);
    cudaGetSymbolAddress((void**)&gmem, g_gmem);
    cudaGetSymbolAddress((void**)&gupd, g_gupd);

    // --- r-branch (big attention) ---
    // K|V projection of memory (shared across batch): (512 x 2048) = mem @ W_kv^T
    sgemm_nt<<<dim3(2 * EE / 128, MM / 128), 256>>>(
        memory, EE, r_in_w + (size_t)EE * EE, EE, r_in_b + EE, nullptr,
        KV, MM, 2 * EE, EE, 1.f);
    // Q projection, prescaled by 1/sqrt(D)=0.125
    sgemm_nt<<<dim3(EE / 128, BB * SS / 128), 256>>>(
        query, EE, r_in_w, EE, r_in_b, nullptr,
        Qp, BB * SS, EE, EE, 0.125f);
    // attention
    attn_kernel<<<dim3(SS / 32, HH, BB), 128>>>(Qp, KV, attn);
    // out projection + residual (+query), then LayerNorm -> out[0 : B*S*E]
    sgemm_nt<<<dim3(EE / 128, BB * SS / 128), 256>>>(
        attn, EE, r_out_w, EE, r_out_b, query,
        y, BB * SS, EE, EE, 1.f);
    ln_kernel<<<BB * SS, 256>>>(y, rn_g, rn_b, out);

    // --- w-branch (collapsed): upd_vec[b] = (wq@Wv^T+bv)@Wo^T+bo ---
    mean_kernel<<<dim3(EE / 32, BB), 256>>>(query, wq);
    gemv8<<<EE / 8, 256>>>(wq, w_in_w + (size_t)2 * EE * EE, EE, w_in_b + 2 * EE, vw, EE, EE);
    gemv8<<<EE / 8, 256>>>(vw, w_out_w, EE, w_out_b, upd, EE, EE);

    // --- gate (decomposed) ---
    // gmem[m,e] = memory[m] @ G1[e]^T + gate_b[e]   (G1 = gate_w[:, :E], ldb=2E)
    sgemm_nt<<<dim3(EE / 128, MM / 128), 256>>>(
        memory, EE, gate_w, 2 * EE, gate_b, nullptr,
        gmem, MM, EE, EE, 1.f);
    // gupd[b,e] = upd[b] @ G2[e]^T                  (G2 = gate_w[:, E:], ldb=2E)
    gemv8<<<EE / 8, 256>>>(upd, gate_w + EE, 2 * EE, nullptr, gupd, EE, EE);

    // new_mem = LN(gate*upd + (1-gate)*mem) -> out[B*S*E : ]
    newmem_kernel<<<BB * MM, 256>>>(gmem, gupd, upd, memory, wn_g, wn_b,
                                    out + (size_t)BB * SS * EE);
}

// round 3
// speedup vs baseline: 1.3014x; 1.3014x over previous
#include <cuda_runtime.h>
#include <cuda_bf16.h>
#include <math.h>
#include <stdint.h>

// ---------------------------------------------------------------------------
// Problem constants
// ---------------------------------------------------------------------------
#define BB 8
#define SS 2048
#define MM 512
#define EE 1024
#define HH 16
#define DD 64

// ---------------------------------------------------------------------------
// Scratch (device globals; no allocation allowed)
// ---------------------------------------------------------------------------
__device__ float g_KV[MM * 2 * EE];
__device__ float g_Qp[BB * SS * EE];
__device__ float g_attn[BB * SS * EE];
__device__ float g_y[BB * SS * EE];
__device__ float g_wq[BB * EE];
__device__ float g_vw[BB * EE];
__device__ float g_upd[BB * EE];
__device__ float g_gmem[MM * EE];
__device__ float g_gupd[BB * EE];

// bf16 hi/lo split buffers
__device__ __nv_bfloat16 g_qh[BB * SS * EE];
__device__ __nv_bfloat16 g_ql[BB * SS * EE];
__device__ __nv_bfloat16 g_ah[BB * SS * EE];
__device__ __nv_bfloat16 g_al[BB * SS * EE];
__device__ __nv_bfloat16 g_mh[MM * EE];
__device__ __nv_bfloat16 g_ml[MM * EE];
__device__ __nv_bfloat16 g_riwh[3 * EE * EE];
__device__ __nv_bfloat16 g_riwl[3 * EE * EE];
__device__ __nv_bfloat16 g_rowh[EE * EE];
__device__ __nv_bfloat16 g_rowl[EE * EE];
__device__ __nv_bfloat16 g_gwh[EE * 2 * EE];
__device__ __nv_bfloat16 g_gwl[EE * 2 * EE];

// ---------------------------------------------------------------------------
// PTX helpers (baseline compute_103 features only: cp.async, ldmatrix, mma)
// ---------------------------------------------------------------------------
__device__ __forceinline__ uint32_t smem_u32(const void* p) {
    uint32_t a;
    asm("{ .reg .u64 t; cvta.to.shared.u64 t, %1; cvt.u32.u64 %0, t; }" : "=r"(a) : "l"(p));
    return a;
}

#define CP_COMMIT() asm volatile("cp.async.commit_group;" ::: "memory")
#define CP_WAIT(n)  asm volatile("cp.async.wait_group %0;" :: "n"(n) : "memory")

__device__ __forceinline__ void cp16(uint32_t saddr, const void* g) {
    asm volatile("cp.async.cg.shared.global [%0], [%1], 16;" :: "r"(saddr), "l"(g) : "memory");
}

__device__ __forceinline__ void ldsm_x4(uint32_t& r0, uint32_t& r1, uint32_t& r2,
                                        uint32_t& r3, uint32_t addr) {
    asm volatile("ldmatrix.sync.aligned.m8n8.x4.shared.b16 {%0,%1,%2,%3}, [%4];"
                 : "=r"(r0), "=r"(r1), "=r"(r2), "=r"(r3) : "r"(addr));
}

__device__ __forceinline__ void mma_16816(float* d, const uint32_t* a,
                                          uint32_t b0, uint32_t b1) {
    asm volatile(
        "mma.sync.aligned.m16n8k16.row.col.f32.bf16.bf16.f32 "
        "{%0,%1,%2,%3}, {%4,%5,%6,%7}, {%8,%9}, {%0,%1,%2,%3};"
        : "+f"(d[0]), "+f"(d[1]), "+f"(d[2]), "+f"(d[3])
        : "r"(a[0]), "r"(a[1]), "r"(a[2]), "r"(a[3]), "r"(b0), "r"(b1));
}

// ---------------------------------------------------------------------------
// hi/lo bf16 split conversion
// ---------------------------------------------------------------------------
__global__ __launch_bounds__(256) void cvt_split(
    const float* __restrict__ x, __nv_bfloat16* __restrict__ hi,
    __nv_bfloat16* __restrict__ lo, int n)
{
    int i = (blockIdx.x * 256 + threadIdx.x) * 4;
    if (i >= n) return;
    float4 v = *(const float4*)(x + i);
    __nv_bfloat16 h0 = __float2bfloat16_rn(v.x);
    __nv_bfloat16 h1 = __float2bfloat16_rn(v.y);
    __nv_bfloat16 h2 = __float2bfloat16_rn(v.z);
    __nv_bfloat16 h3 = __float2bfloat16_rn(v.w);
    __nv_bfloat16 l0 = __float2bfloat16_rn(v.x - __bfloat162float(h0));
    __nv_bfloat16 l1 = __float2bfloat16_rn(v.y - __bfloat162float(h1));
    __nv_bfloat16 l2 = __float2bfloat16_rn(v.z - __bfloat162float(h2));
    __nv_bfloat16 l3 = __float2bfloat16_rn(v.w - __bfloat162float(h3));
    *(__nv_bfloat162*)(hi + i)     = __halves2bfloat162(h0, h1);
    *(__nv_bfloat162*)(hi + i + 2) = __halves2bfloat162(h2, h3);
    *(__nv_bfloat162*)(lo + i)     = __halves2bfloat162(l0, l1);
    *(__nv_bfloat162*)(lo + i + 2) = __halves2bfloat162(l2, l3);
}

// ---------------------------------------------------------------------------
// HMMA split-bf16 GEMM (NT):
//   C[Mr,N] = scale * ((Ah+Al)[Mr,1024] @ (Bh+Bl)[N,1024]^T + bias[N]) + res
// 3 bf16 passes accumulated in fp32 registers. Tile 128x128, BK=32,
// 4-stage cp.async pipeline. grid=(N/128, Mr/128), 256 threads,
// dynamic smem = 64KB.
// ---------------------------------------------------------------------------
#define GSTAGE 16384
#define GSMEM  (4 * GSTAGE)

__global__ __launch_bounds__(256, 1) void gemm_mma(
    const __nv_bfloat16* __restrict__ Ah, const __nv_bfloat16* __restrict__ Al, int lda,
    const __nv_bfloat16* __restrict__ Bh, const __nv_bfloat16* __restrict__ Bl, int ldb,
    const float* __restrict__ bias, const float* __restrict__ res,
    float* __restrict__ C, int N, float scale)
{
    extern __shared__ char smem[];
    const uint32_t sbase = smem_u32(smem);
    const int tid = threadIdx.x;
    const int wid = tid >> 5, lane = tid & 31;
    const int wm = wid >> 2, wn = wid & 3;       // 2 x 4 warp grid
    const int mbase = blockIdx.y * 128;
    const int nbase = blockIdx.x * 128;

    const __nv_bfloat16* APass[3] = {Ah, Ah, Al};
    const __nv_bfloat16* BPass[3] = {Bh, Bl, Bh};

    float acc[4][4][4];
#pragma unroll
    for (int i = 0; i < 4; i++)
#pragma unroll
        for (int j = 0; j < 4; j++)
#pragma unroll
            for (int k = 0; k < 4; k++) acc[i][j][k] = 0.f;

    // ---- stage loader: A/B tiles 128x32 bf16, swizzled (c ^= (row>>1)&3) ----
    auto load_stage = [&](int s, int buf) {
        int p = s >> 5, kt = s & 31;
        const __nv_bfloat16* As = APass[p];
        const __nv_bfloat16* Bs = BPass[p];
        uint32_t sA = sbase + (uint32_t)buf * GSTAGE;
        uint32_t sB = sA + 8192;
#pragma unroll
        for (int j = 0; j < 2; j++) {
            int u = tid + j * 256;            // 0..511
            int r = u >> 2, c = u & 3;
            int cs = c ^ ((r >> 1) & 3);
            cp16(sA + r * 64 + cs * 16, As + (size_t)(mbase + r) * lda + kt * 32 + c * 8);
        }
#pragma unroll
        for (int j = 0; j < 2; j++) {
            int u = tid + j * 256;
            int r = u >> 2, c = u & 3;
            int cs = c ^ ((r >> 1) & 3);
            cp16(sB + r * 64 + cs * 16, Bs + (size_t)(nbase + r) * ldb + kt * 32 + c * 8);
        }
    };

    const int NST = 96;   // 3 passes * 32 k-chunks
    load_stage(0, 0); CP_COMMIT();
    load_stage(1, 1); CP_COMMIT();
    load_stage(2, 2); CP_COMMIT();

    for (int s = 0; s < NST; ++s) {
        int pf = s + 3;
        if (pf < NST) {
            load_stage(pf, pf & 3);
            CP_COMMIT();
            CP_WAIT(3);
        } else {
            CP_WAIT(0);
        }
        __syncthreads();

        uint32_t sA = sbase + (uint32_t)(s & 3) * GSTAGE;
        uint32_t sB = sA + 8192;

#pragma unroll
        for (int kk = 0; kk < 2; kk++) {
            uint32_t a[4][4];
#pragma unroll
            for (int mi = 0; mi < 4; mi++) {
                int r = wm * 64 + mi * 16 + (lane & 15);
                int c = kk * 2 + (lane >> 4);
                int cs = c ^ ((r >> 1) & 3);
                ldsm_x4(a[mi][0], a[mi][1], a[mi][2], a[mi][3], sA + r * 64 + cs * 16);
            }
            uint32_t b[2][4];
#pragma unroll
            for (int nb = 0; nb < 2; nb++) {
                int r = wn * 32 + nb * 16 + ((lane >> 4) << 3) + (lane & 7);
                int c = kk * 2 + ((lane >> 3) & 1);
                int cs = c ^ ((r >> 1) & 3);
                ldsm_x4(b[nb][0], b[nb][1], b[nb][2], b[nb][3], sB + r * 64 + cs * 16);
            }
#pragma unroll
            for (int mi = 0; mi < 4; mi++)
#pragma unroll
                for (int ni = 0; ni < 4; ni++) {
                    int nb = ni >> 1, h = ni & 1;
                    mma_16816(acc[mi][ni], a[mi], b[nb][h * 2], b[nb][h * 2 + 1]);
                }
        }
        __syncthreads();
    }

    // ---- epilogue ----
    const int r_lo = lane >> 2;
    const int c_off = (lane & 3) * 2;
#pragma unroll
    for (int mi = 0; mi < 4; mi++) {
        size_t row = (size_t)mbase + wm * 64 + mi * 16 + r_lo;
#pragma unroll
        for (int ni = 0; ni < 4; ni++) {
            int col = nbase + wn * 32 + ni * 8 + c_off;
            const float* a4 = acc[mi][ni];
            float2 bv = *(const float2*)(bias + col);
            float2 v0, v1;
            v0.x = scale * (a4[0] + bv.x); v0.y = scale * (a4[1] + bv.y);
            v1.x = scale * (a4[2] + bv.x); v1.y = scale * (a4[3] + bv.y);
            if (res) {
                float2 r0 = *(const float2*)(res + row * N + col);
                float2 r1 = *(const float2*)(res + (row + 8) * N + col);
                v0.x += r0.x; v0.y += r0.y; v1.x += r1.x; v1.y += r1.y;
            }
            *(float2*)(C + row * N + col) = v0;
            *(float2*)(C + (row + 8) * N + col) = v1;
        }
    }
}

// ---------------------------------------------------------------------------
// Flash-style attention (fp32, unchanged from passing R1 kernel).
// ---------------------------------------------------------------------------
__global__ __launch_bounds__(128) void attn_kernel(
    const float* __restrict__ Qp,
    const float* __restrict__ KV,
    float* __restrict__ O)
{
    __shared__ float Qt[64][36];
    __shared__ float Kt[64][68];
    __shared__ float Vs[64][68];

    const int b = blockIdx.z, h = blockIdx.y;
    const int s0 = blockIdx.x * 32;
    const int tid = threadIdx.x;
    const int tx = tid & 15, ty = tid >> 4;

    {
        int q = tid >> 2;
        int d0 = (tid & 3) * 16;
        const float* src = Qp + ((size_t)(b * SS + s0 + q)) * EE + h * DD + d0;
#pragma unroll
        for (int i = 0; i < 4; i++) {
            float4 v = *(const float4*)(src + i * 4);
            Qt[d0 + i * 4 + 0][q] = v.x; Qt[d0 + i * 4 + 1][q] = v.y;
            Qt[d0 + i * 4 + 2][q] = v.z; Qt[d0 + i * 4 + 3][q] = v.w;
        }
    }

    float o[4][4];
#pragma unroll
    for (int i = 0; i < 4; i++)
#pragma unroll
        for (int j = 0; j < 4; j++) o[i][j] = 0.f;
    float mrow[4] = {-1e30f, -1e30f, -1e30f, -1e30f};
    float lrow[4] = {0.f, 0.f, 0.f, 0.f};

    float* Ps = &Kt[0][0];

    for (int kc = 0; kc < MM / 64; kc++) {
        const int k0 = kc * 64;
        __syncthreads();
        {
            int j = tid >> 1;
            int d0 = (tid & 1) * 32;
            const float* ksrc = KV + (size_t)(k0 + j) * (2 * EE) + h * DD + d0;
            const float* vsrc = ksrc + EE;
#pragma unroll
            for (int i = 0; i < 8; i++) {
                float4 kv4 = *(const float4*)(ksrc + i * 4);
                Kt[d0 + i * 4 + 0][j] = kv4.x; Kt[d0 + i * 4 + 1][j] = kv4.y;
                Kt[d0 + i * 4 + 2][j] = kv4.z; Kt[d0 + i * 4 + 3][j] = kv4.w;
            }
#pragma unroll
            for (int i = 0; i < 8; i++)
                *(float4*)&Vs[j][d0 + i * 4] = *(const float4*)(vsrc + i * 4);
        }
        __syncthreads();

        float acc[4][4];
#pragma unroll
        for (int i = 0; i < 4; i++)
#pragma unroll
            for (int j = 0; j < 4; j++) acc[i][j] = 0.f;
#pragma unroll 4
        for (int d = 0; d < 64; d++) {
            float4 qv = *(float4*)&Qt[d][ty * 4];
            float4 kv = *(float4*)&Kt[d][tx * 4];
            float qa[4] = {qv.x, qv.y, qv.z, qv.w};
            float ka[4] = {kv.x, kv.y, kv.z, kv.w};
#pragma unroll
            for (int qi = 0; qi < 4; qi++)
#pragma unroll
                for (int ji = 0; ji < 4; ji++)
                    acc[qi][ji] = fmaf(qa[qi], ka[ji], acc[qi][ji]);
        }

#pragma unroll
        for (int qi = 0; qi < 4; qi++) {
            float tm = fmaxf(fmaxf(acc[qi][0], acc[qi][1]), fmaxf(acc[qi][2], acc[qi][3]));
#pragma unroll
            for (int off = 8; off >= 1; off >>= 1)
                tm = fmaxf(tm, __shfl_xor_sync(0xffffffffu, tm, off));
            float newm = fmaxf(mrow[qi], tm);
            float fac = __expf(mrow[qi] - newm);
            float ps = 0.f;
#pragma unroll
            for (int ji = 0; ji < 4; ji++) {
                acc[qi][ji] = __expf(acc[qi][ji] - newm);
                ps += acc[qi][ji];
            }
#pragma unroll
            for (int off = 8; off >= 1; off >>= 1)
                ps += __shfl_xor_sync(0xffffffffu, ps, off);
            lrow[qi] = lrow[qi] * fac + ps;
            mrow[qi] = newm;
#pragma unroll
            for (int di = 0; di < 4; di++) o[qi][di] *= fac;
        }
        __syncthreads();

#pragma unroll
        for (int ji = 0; ji < 4; ji++)
#pragma unroll
            for (int qi = 0; qi < 4; qi++)
                Ps[(tx * 4 + ji) * 36 + ty * 4 + qi] = acc[qi][ji];
        __syncthreads();

#pragma unroll 4
        for (int j = 0; j < 64; j++) {
            float4 pv = *(float4*)&Ps[j * 36 + ty * 4];
            float4 vv = *(float4*)&Vs[j][tx * 4];
            float pa[4] = {pv.x, pv.y, pv.z, pv.w};
            float va[4] = {vv.x, vv.y, vv.z, vv.w};
#pragma unroll
            for (int qi = 0; qi < 4; qi++)
#pragma unroll
                for (int di = 0; di < 4; di++)
                    o[qi][di] = fmaf(pa[qi], va[di], o[qi][di]);
        }
    }

#pragma unroll
    for (int qi = 0; qi < 4; qi++) {
        float inv = 1.f / lrow[qi];
        float4 v;
        v.x = o[qi][0] * inv; v.y = o[qi][1] * inv;
        v.z = o[qi][2] * inv; v.w = o[qi][3] * inv;
        *(float4*)&O[((size_t)(b * SS + s0 + ty * 4 + qi)) * EE + h * DD + tx * 4] = v;
    }
}

// ---------------------------------------------------------------------------
// Pointwise / reduction kernels
// ---------------------------------------------------------------------------
__device__ __forceinline__ void block_reduce2(float& s1, float& s2) {
    __shared__ float r1[8], r2[8];
    int lane = threadIdx.x & 31, w = threadIdx.x >> 5;
#pragma unroll
    for (int off = 16; off; off >>= 1) {
        s1 += __shfl_xor_sync(0xffffffffu, s1, off);
        s2 += __shfl_xor_sync(0xffffffffu, s2, off);
    }
    if (lane == 0) { r1[w] = s1; r2[w] = s2; }
    __syncthreads();
    if (w == 0) {
        s1 = (lane < 8) ? r1[lane] : 0.f;
        s2 = (lane < 8) ? r2[lane] : 0.f;
#pragma unroll
        for (int off = 4; off; off >>= 1) {
            s1 += __shfl_xor_sync(0xffffffffu, s1, off);
            s2 += __shfl_xor_sync(0xffffffffu, s2, off);
        }
        if (lane == 0) { r1[0] = s1; r2[0] = s2; }
    }
    __syncthreads();
    s1 = r1[0]; s2 = r2[0];
}

__global__ __launch_bounds__(256) void ln_kernel(
    const float* __restrict__ X, const float* __restrict__ g,
    const float* __restrict__ bta, float* __restrict__ out)
{
    size_t row = blockIdx.x;
    const float* x = X + row * EE;
    int c = threadIdx.x * 4;
    float4 v = *(const float4*)(x + c);
    float s1 = v.x + v.y + v.z + v.w;
    float s2 = v.x * v.x + v.y * v.y + v.z * v.z + v.w * v.w;
    block_reduce2(s1, s2);
    float mu = s1 * (1.f / EE);
    float var = s2 * (1.f / EE) - mu * mu;
    float rs = rsqrtf(var + 1e-5f);
    float4 gg = *(const float4*)(g + c);
    float4 bb = *(const float4*)(bta + c);
    float4 o;
    o.x = (v.x - mu) * rs * gg.x + bb.x;
    o.y = (v.y - mu) * rs * gg.y + bb.y;
    o.z = (v.z - mu) * rs * gg.z + bb.z;
    o.w = (v.w - mu) * rs * gg.w + bb.w;
    *(float4*)(out + row * EE + c) = o;
}

__global__ __launch_bounds__(256) void newmem_kernel(
    const float* __restrict__ gmemM,
    const float* __restrict__ gupd,
    const float* __restrict__ upd,
    const float* __restrict__ memv,
    const float* __restrict__ wg, const float* __restrict__ wb,
    float* __restrict__ out)
{
    int row = blockIdx.x;
    int b = row >> 9, m = row & 511;
    int c = threadIdx.x * 4;
    float4 gm = *(const float4*)(gmemM + (size_t)m * EE + c);
    float4 gu = *(const float4*)(gupd + (size_t)b * EE + c);
    float4 uv = *(const float4*)(upd + (size_t)b * EE + c);
    float4 mv = *(const float4*)(memv + (size_t)m * EE + c);
    float ge[4] = {gm.x + gu.x, gm.y + gu.y, gm.z + gu.z, gm.w + gu.w};
    float u[4] = {uv.x, uv.y, uv.z, uv.w};
    float mmv[4] = {mv.x, mv.y, mv.z, mv.w};
    float x[4];
    float s1 = 0.f, s2 = 0.f;
#pragma unroll
    for (int i = 0; i < 4; i++) {
        float gt = 1.f / (1.f + __expf(-ge[i]));
        x[i] = gt * u[i] + (1.f - gt) * mmv[i];
        s1 += x[i]; s2 += x[i] * x[i];
    }
    block_reduce2(s1, s2);
    float mu = s1 * (1.f / EE);
    float var = s2 * (1.f / EE) - mu * mu;
    float rs = rsqrtf(var + 1e-5f);
    float4 gg = *(const float4*)(wg + c);
    float4 bb = *(const float4*)(wb + c);
    float4 o;
    o.x = (x[0] - mu) * rs * gg.x + bb.x;
    o.y = (x[1] - mu) * rs * gg.y + bb.y;
    o.z = (x[2] - mu) * rs * gg.z + bb.z;
    o.w = (x[3] - mu) * rs * gg.w + bb.w;
    *(float4*)(out + (size_t)row * EE + c) = o;
}

__global__ __launch_bounds__(256) void mean_kernel(
    const float* __restrict__ q, float* __restrict__ wq)
{
    __shared__ float red[8][33];
    int b = blockIdx.y;
    int e0 = blockIdx.x * 32;
    int el = threadIdx.x & 31, strip = threadIdx.x >> 5;
    const float* p = q + ((size_t)b * SS + strip * 256) * EE + e0 + el;
    float s = 0.f;
#pragma unroll 4
    for (int i = 0; i < 256; i++) s += p[(size_t)i * EE];
    red[strip][el] = s;
    __syncthreads();
    if (strip == 0) {
        float t = 0.f;
#pragma unroll
        for (int k = 0; k < 8; k++) t += red[k][el];
        wq[(size_t)b * EE + e0 + el] = t * (1.f / SS);
    }
}

__global__ __launch_bounds__(256) void gemv8(
    const float* __restrict__ A,
    const float* __restrict__ B, int ldb,
    const float* __restrict__ bias,
    float* __restrict__ C, int N, int K)
{
    int w = threadIdx.x >> 5, lane = threadIdx.x & 31;
    int n = blockIdx.x * 8 + w;
    if (n >= N) return;
    const float* brow = B + (size_t)n * ldb;
    for (int b = 0; b < BB; b++) {
        const float* arow = A + (size_t)b * K;
        float s = 0.f;
        for (int i = lane; i < K; i += 32) s += arow[i] * brow[i];
#pragma unroll
        for (int off = 16; off; off >>= 1) s += __shfl_xor_sync(0xffffffffu, s, off);
        if (lane == 0) C[(size_t)b * N + n] = s + (bias ? bias[n] : 0.f);
    }
}

// ---------------------------------------------------------------------------
extern "C" void kernel_launch(void* const* d_in, const int* in_sizes, int n_in,
                              void* d_out, int out_size)
{
    (void)in_sizes; (void)n_in; (void)out_size;
    const float* query   = (const float*)d_in[0];
    const float* memory  = (const float*)d_in[1];
    const float* r_in_w  = (const float*)d_in[2];
    const float* r_in_b  = (const float*)d_in[3];
    const float* r_out_w = (const float*)d_in[4];
    const float* r_out_b = (const float*)d_in[5];
    const float* w_in_w  = (const float*)d_in[6];
    const float* w_in_b  = (const float*)d_in[7];
    const float* w_out_w = (const float*)d_in[8];
    const float* w_out_b = (const float*)d_in[9];
    const float* rn_g    = (const float*)d_in[10];
    const float* rn_b    = (const float*)d_in[11];
    const float* wn_g    = (const float*)d_in[12];
    const float* wn_b    = (const float*)d_in[13];
    const float* gate_w  = (const float*)d_in[14];
    const float* gate_b  = (const float*)d_in[15];
    float* out = (float*)d_out;

    float *KV, *Qp, *attn, *y, *wq, *vw, *upd, *gmem, *gupd;
    cudaGetSymbolAddress((void**)&KV,   g_KV);
    cudaGetSymbolAddress((void**)&Qp,   g_Qp);
    cudaGetSymbolAddress((void**)&attn, g_attn);
    cudaGetSymbolAddress((void**)&y,    g_y);
    cudaGetSymbolAddress((void**)&wq,   g_wq);
    cudaGetSymbolAddress((void**)&vw,   g_vw);
    cudaGetSymbolAddress((void**)&upd,  g_upd);
    cudaGetSymbolAddress((void**)&gmem, g_gmem);
    cudaGetSymbolAddress((void**)&gupd, g_gupd);

    __nv_bfloat16 *qh, *ql, *ah, *al, *mh, *ml, *riwh, *riwl, *rowh, *rowl, *gwh, *gwl;
    cudaGetSymbolAddress((void**)&qh,   g_qh);
    cudaGetSymbolAddress((void**)&ql,   g_ql);
    cudaGetSymbolAddress((void**)&ah,   g_ah);
    cudaGetSymbolAddress((void**)&al,   g_al);
    cudaGetSymbolAddress((void**)&mh,   g_mh);
    cudaGetSymbolAddress((void**)&ml,   g_ml);
    cudaGetSymbolAddress((void**)&riwh, g_riwh);
    cudaGetSymbolAddress((void**)&riwl, g_riwl);
    cudaGetSymbolAddress((void**)&rowh, g_rowh);
    cudaGetSymbolAddress((void**)&rowl, g_rowl);
    cudaGetSymbolAddress((void**)&gwh,  g_gwh);
    cudaGetSymbolAddress((void**)&gwl,  g_gwl);

    cudaFuncSetAttribute(gemm_mma, cudaFuncAttributeMaxDynamicSharedMemorySize, GSMEM);

    // --- split conversions ---
    cvt_split<<<3 * EE * EE / 1024, 256>>>(r_in_w, riwh, riwl, 3 * EE * EE);
    cvt_split<<<EE * EE / 1024, 256>>>(r_out_w, rowh, rowl, EE * EE);
    cvt_split<<<2 * EE * EE / 1024, 256>>>(gate_w, gwh, gwl, 2 * EE * EE);
    cvt_split<<<MM * EE / 1024, 256>>>(memory, mh, ml, MM * EE);
    cvt_split<<<BB * SS * EE / 1024, 256>>>(query, qh, ql, BB * SS * EE);

    // --- r-branch ---
    // KV projection (shared across batch): (512 x 2048)
    gemm_mma<<<dim3(2 * EE / 128, MM / 128), 256, GSMEM>>>(
        mh, ml, EE, riwh + (size_t)EE * EE, riwl + (size_t)EE * EE, EE,
        r_in_b + EE, nullptr, KV, 2 * EE, 1.f);
    // Q projection, prescaled by 1/sqrt(D)
    gemm_mma<<<dim3(EE / 128, BB * SS / 128), 256, GSMEM>>>(
        qh, ql, EE, riwh, riwl, EE,
        r_in_b, nullptr, Qp, EE, 0.125f);
    // attention
    attn_kernel<<<dim3(SS / 32, HH, BB), 128>>>(Qp, KV, attn);
    // out projection + residual + LN
    cvt_split<<<BB * SS * EE / 1024, 256>>>(attn, ah, al, BB * SS * EE);
    gemm_mma<<<dim3(EE / 128, BB * SS / 128), 256, GSMEM>>>(
        ah, al, EE, rowh, rowl, EE,
        r_out_b, query, y, EE, 1.f);
    ln_kernel<<<BB * SS, 256>>>(y, rn_g, rn_b, out);

    // --- w-branch (collapsed) ---
    mean_kernel<<<dim3(EE / 32, BB), 256>>>(query, wq);
    gemv8<<<EE / 8, 256>>>(wq, w_in_w + (size_t)2 * EE * EE, EE, w_in_b + 2 * EE, vw, EE, EE);
    gemv8<<<EE / 8, 256>>>(vw, w_out_w, EE, w_out_b, upd, EE, EE);

    // --- gate (decomposed) ---
    gemm_mma<<<dim3(EE / 128, MM / 128), 256, GSMEM>>>(
        mh, ml, EE, gwh, gwl, 2 * EE,
        gate_b, nullptr, gmem, EE, 1.f);
    gemv8<<<EE / 8, 256>>>(upd, gate_w + EE, 2 * EE, nullptr, gupd, EE, EE);

    newmem_kernel<<<BB * MM, 256>>>(gmem, gupd, upd, memory, wn_g, wn_b,
                                    out + (size_t)BB * SS * EE);
}

// round 5
// speedup vs baseline: 2.3549x; 1.8095x over previous
#include <cuda_runtime.h>
#include <cuda_bf16.h>
#include <math.h>
#include <stdint.h>

// ---------------------------------------------------------------------------
// Problem constants
// ---------------------------------------------------------------------------
#define BB 8
#define SS 2048
#define MM 512
#define EE 1024
#define HH 16
#define DD 64

// ---------------------------------------------------------------------------
// Scratch (device globals; no allocation allowed)
// ---------------------------------------------------------------------------
__device__ float g_KV[MM * 2 * EE];
__device__ float g_y[BB * SS * EE];
__device__ float g_wq[BB * EE];
__device__ float g_vw[BB * EE];
__device__ float g_upd[BB * EE];
__device__ float g_gmem[MM * EE];
__device__ float g_gupd[BB * EE];

// bf16 hi/lo split buffers
__device__ __nv_bfloat16 g_qh[BB * SS * EE];      // query split (GEMM A input)
__device__ __nv_bfloat16 g_ql[BB * SS * EE];
__device__ __nv_bfloat16 g_qph[BB * SS * EE];     // Q-proj output split
__device__ __nv_bfloat16 g_qpl[BB * SS * EE];
__device__ __nv_bfloat16 g_ah[BB * SS * EE];      // attention output split
__device__ __nv_bfloat16 g_al[BB * SS * EE];
__device__ __nv_bfloat16 g_mh[MM * EE];
__device__ __nv_bfloat16 g_ml[MM * EE];
__device__ __nv_bfloat16 g_kh[MM * EE];           // K split [j][e]
__device__ __nv_bfloat16 g_kl[MM * EE];
__device__ __nv_bfloat16 g_vth[EE * MM];          // V transposed split [e][j]
__device__ __nv_bfloat16 g_vtl[EE * MM];
__device__ __nv_bfloat16 g_riwh[3 * EE * EE];
__device__ __nv_bfloat16 g_riwl[3 * EE * EE];
__device__ __nv_bfloat16 g_rowh[EE * EE];
__device__ __nv_bfloat16 g_rowl[EE * EE];
__device__ __nv_bfloat16 g_gwh[EE * 2 * EE];
__device__ __nv_bfloat16 g_gwl[EE * 2 * EE];

// ---------------------------------------------------------------------------
// PTX helpers (baseline compute_103 features only: cp.async, ldmatrix, mma)
// ---------------------------------------------------------------------------
__device__ __forceinline__ uint32_t smem_u32(const void* p) {
    uint32_t a;
    asm("{ .reg .u64 t; cvta.to.shared.u64 t, %1; cvt.u32.u64 %0, t; }" : "=r"(a) : "l"(p));
    return a;
}

#define CP_COMMIT() asm volatile("cp.async.commit_group;" ::: "memory")
#define CP_WAIT(n)  asm volatile("cp.async.wait_group %0;" :: "n"(n) : "memory")

__device__ __forceinline__ void cp16(uint32_t saddr, const void* g) {
    asm volatile("cp.async.cg.shared.global [%0], [%1], 16;" :: "r"(saddr), "l"(g) : "memory");
}

__device__ __forceinline__ void ldsm_x4(uint32_t& r0, uint32_t& r1, uint32_t& r2,
                                        uint32_t& r3, uint32_t addr) {
    asm volatile("ldmatrix.sync.aligned.m8n8.x4.shared.b16 {%0,%1,%2,%3}, [%4];"
                 : "=r"(r0), "=r"(r1), "=r"(r2), "=r"(r3) : "r"(addr));
}

__device__ __forceinline__ void mma_16816(float* d, const uint32_t* a,
                                          uint32_t b0, uint32_t b1) {
    asm volatile(
        "mma.sync.aligned.m16n8k16.row.col.f32.bf16.bf16.f32 "
        "{%0,%1,%2,%3}, {%4,%5,%6,%7}, {%8,%9}, {%0,%1,%2,%3};"
        : "+f"(d[0]), "+f"(d[1]), "+f"(d[2]), "+f"(d[3])
        : "r"(a[0]), "r"(a[1]), "r"(a[2]), "r"(a[3]), "r"(b0), "r"(b1));
}

__device__ __forceinline__ uint32_t pack_bf2(float a, float b) {
    __nv_bfloat162 t = __floats2bfloat162_rn(a, b);
    return *reinterpret_cast<uint32_t*>(&t);
}
__device__ __forceinline__ float bf_res(float x) {
    return x - __bfloat162float(__float2bfloat16_rn(x));
}

// ---------------------------------------------------------------------------
// hi/lo bf16 split conversion
// ---------------------------------------------------------------------------
__global__ __launch_bounds__(256) void cvt_split(
    const float* __restrict__ x, __nv_bfloat16* __restrict__ hi,
    __nv_bfloat16* __restrict__ lo, int n)
{
    int i = (blockIdx.x * 256 + threadIdx.x) * 4;
    if (i >= n) return;
    float4 v = *(const float4*)(x + i);
    __nv_bfloat16 h0 = __float2bfloat16_rn(v.x);
    __nv_bfloat16 h1 = __float2bfloat16_rn(v.y);
    __nv_bfloat16 h2 = __float2bfloat16_rn(v.z);
    __nv_bfloat16 h3 = __float2bfloat16_rn(v.w);
    *(__nv_bfloat162*)(hi + i)     = __halves2bfloat162(h0, h1);
    *(__nv_bfloat162*)(hi + i + 2) = __halves2bfloat162(h2, h3);
    *(__nv_bfloat162*)(lo + i)     = __halves2bfloat162(
        __float2bfloat16_rn(v.x - __bfloat162float(h0)),
        __float2bfloat16_rn(v.y - __bfloat162float(h1)));
    *(__nv_bfloat162*)(lo + i + 2) = __halves2bfloat162(
        __float2bfloat16_rn(v.z - __bfloat162float(h2)),
        __float2bfloat16_rn(v.w - __bfloat162float(h3)));
}

// ---------------------------------------------------------------------------
// KV prep: K part -> direct row-major split; V part -> transposed split.
// ---------------------------------------------------------------------------
__global__ __launch_bounds__(256) void split_k(
    const float* __restrict__ KV, __nv_bfloat16* __restrict__ kh,
    __nv_bfloat16* __restrict__ kl)
{
    int j = blockIdx.x;
    int c = threadIdx.x * 4;
    float4 v = *(const float4*)(KV + (size_t)j * (2 * EE) + c);
    __nv_bfloat16 h0 = __float2bfloat16_rn(v.x);
    __nv_bfloat16 h1 = __float2bfloat16_rn(v.y);
    __nv_bfloat16 h2 = __float2bfloat16_rn(v.z);
    __nv_bfloat16 h3 = __float2bfloat16_rn(v.w);
    size_t o = (size_t)j * EE + c;
    *(__nv_bfloat162*)(kh + o)     = __halves2bfloat162(h0, h1);
    *(__nv_bfloat162*)(kh + o + 2) = __halves2bfloat162(h2, h3);
    *(__nv_bfloat162*)(kl + o)     = __halves2bfloat162(
        __float2bfloat16_rn(v.x - __bfloat162float(h0)),
        __float2bfloat16_rn(v.y - __bfloat162float(h1)));
    *(__nv_bfloat162*)(kl + o + 2) = __halves2bfloat162(
        __float2bfloat16_rn(v.z - __bfloat162float(h2)),
        __float2bfloat16_rn(v.w - __bfloat162float(h3)));
}

__global__ __launch_bounds__(256) void transpose_v(
    const float* __restrict__ KV, __nv_bfloat16* __restrict__ vth,
    __nv_bfloat16* __restrict__ vtl)
{
    __shared__ float t[32][33];
    int e0 = blockIdx.x * 32, j0 = blockIdx.y * 32;
    int tx = threadIdx.x & 31, ty = threadIdx.x >> 5;
#pragma unroll
    for (int k2 = 0; k2 < 4; k2++)
        t[ty + k2 * 8][tx] = KV[(size_t)(j0 + ty + k2 * 8) * (2 * EE) + EE + e0 + tx];
    __syncthreads();
#pragma unroll
    for (int k2 = 0; k2 < 4; k2++) {
        float v = t[tx][ty + k2 * 8];
        __nv_bfloat16 hv = __float2bfloat16_rn(v);
        size_t o = (size_t)(e0 + ty + k2 * 8) * MM + j0 + tx;
        vth[o] = hv;
        vtl[o] = __float2bfloat16_rn(v - __bfloat162float(hv));
    }
}

// ---------------------------------------------------------------------------
// HMMA split-bf16 GEMM (NT):
//   C = scale * ((Ah+Al) @ (Bh+Bl)^T + bias) [+ res]   (3 bf16 passes)
// If Chi != null: write bf16 hi/lo split output instead of fp32.
// ---------------------------------------------------------------------------
#define GSTAGE 16384
#define GSMEM  (4 * GSTAGE)

__global__ __launch_bounds__(256, 1) void gemm_mma(
    const __nv_bfloat16* __restrict__ Ah, const __nv_bfloat16* __restrict__ Al, int lda,
    const __nv_bfloat16* __restrict__ Bh, const __nv_bfloat16* __restrict__ Bl, int ldb,
    const float* __restrict__ bias, const float* __restrict__ res,
    float* __restrict__ C,
    __nv_bfloat16* __restrict__ Chi, __nv_bfloat16* __restrict__ Clo,
    int N, float scale)
{
    extern __shared__ char smem[];
    const uint32_t sbase = smem_u32(smem);
    const int tid = threadIdx.x;
    const int wid = tid >> 5, lane = tid & 31;
    const int wm = wid >> 2, wn = wid & 3;
    const int mbase = blockIdx.y * 128;
    const int nbase = blockIdx.x * 128;

    const __nv_bfloat16* APass[3] = {Ah, Ah, Al};
    const __nv_bfloat16* BPass[3] = {Bh, Bl, Bh};

    float acc[4][4][4];
#pragma unroll
    for (int i = 0; i < 4; i++)
#pragma unroll
        for (int j = 0; j < 4; j++)
#pragma unroll
            for (int k = 0; k < 4; k++) acc[i][j][k] = 0.f;

    auto load_stage = [&](int s, int buf) {
        int p = s >> 5, kt = s & 31;
        const __nv_bfloat16* As = APass[p];
        const __nv_bfloat16* Bs = BPass[p];
        uint32_t sA = sbase + (uint32_t)buf * GSTAGE;
        uint32_t sB = sA + 8192;
#pragma unroll
        for (int j = 0; j < 2; j++) {
            int u = tid + j * 256;
            int r = u >> 2, c = u & 3;
            int cs = c ^ ((r >> 1) & 3);
            cp16(sA + r * 64 + cs * 16, As + (size_t)(mbase + r) * lda + kt * 32 + c * 8);
        }
#pragma unroll
        for (int j = 0; j < 2; j++) {
            int u = tid + j * 256;
            int r = u >> 2, c = u & 3;
            int cs = c ^ ((r >> 1) & 3);
            cp16(sB + r * 64 + cs * 16, Bs + (size_t)(nbase + r) * ldb + kt * 32 + c * 8);
        }
    };

    const int NST = 96;
    load_stage(0, 0); CP_COMMIT();
    load_stage(1, 1); CP_COMMIT();
    load_stage(2, 2); CP_COMMIT();

    for (int s = 0; s < NST; ++s) {
        int pf = s + 3;
        if (pf < NST) {
            load_stage(pf, pf & 3);
            CP_COMMIT();
            CP_WAIT(3);
        } else {
            CP_WAIT(0);
        }
        __syncthreads();

        uint32_t sA = sbase + (uint32_t)(s & 3) * GSTAGE;
        uint32_t sB = sA + 8192;

#pragma unroll
        for (int kk = 0; kk < 2; kk++) {
            uint32_t a[4][4];
#pragma unroll
            for (int mi = 0; mi < 4; mi++) {
                int r = wm * 64 + mi * 16 + (lane & 15);
                int c = kk * 2 + (lane >> 4);
                int cs = c ^ ((r >> 1) & 3);
                ldsm_x4(a[mi][0], a[mi][1], a[mi][2], a[mi][3], sA + r * 64 + cs * 16);
            }
            uint32_t b[2][4];
#pragma unroll
            for (int nb = 0; nb < 2; nb++) {
                int r = wn * 32 + nb * 16 + ((lane >> 4) << 3) + (lane & 7);
                int c = kk * 2 + ((lane >> 3) & 1);
                int cs = c ^ ((r >> 1) & 3);
                ldsm_x4(b[nb][0], b[nb][1], b[nb][2], b[nb][3], sB + r * 64 + cs * 16);
            }
#pragma unroll
            for (int mi = 0; mi < 4; mi++)
#pragma unroll
                for (int ni = 0; ni < 4; ni++) {
                    int nb = ni >> 1, hh = ni & 1;
                    mma_16816(acc[mi][ni], a[mi], b[nb][hh * 2], b[nb][hh * 2 + 1]);
                }
        }
        __syncthreads();
    }

    // ---- epilogue ----
    const int r_lo = lane >> 2;
    const int c_off = (lane & 3) * 2;
#pragma unroll
    for (int mi = 0; mi < 4; mi++) {
        size_t row = (size_t)mbase + wm * 64 + mi * 16 + r_lo;
#pragma unroll
        for (int ni = 0; ni < 4; ni++) {
            int col = nbase + wn * 32 + ni * 8 + c_off;
            const float* a4 = acc[mi][ni];
            float2 bv = *(const float2*)(bias + col);
            float2 v0, v1;
            v0.x = scale * (a4[0] + bv.x); v0.y = scale * (a4[1] + bv.y);
            v1.x = scale * (a4[2] + bv.x); v1.y = scale * (a4[3] + bv.y);
            if (Chi) {
                *(uint32_t*)(Chi + row * N + col)       = pack_bf2(v0.x, v0.y);
                *(uint32_t*)(Chi + (row + 8) * N + col) = pack_bf2(v1.x, v1.y);
                *(uint32_t*)(Clo + row * N + col)       = pack_bf2(bf_res(v0.x), bf_res(v0.y));
                *(uint32_t*)(Clo + (row + 8) * N + col) = pack_bf2(bf_res(v1.x), bf_res(v1.y));
            } else {
                if (res) {
                    float2 r0 = *(const float2*)(res + row * N + col);
                    float2 r1 = *(const float2*)(res + (row + 8) * N + col);
                    v0.x += r0.x; v0.y += r0.y; v1.x += r1.x; v1.y += r1.y;
                }
                *(float2*)(C + row * N + col) = v0;
                *(float2*)(C + (row + 8) * N + col) = v1;
            }
        }
    }
}

// ---------------------------------------------------------------------------
// HMMA flash attention. 64 q-rows per block, 4 warps x 16 rows, 8 key chunks
// of 64. 3-pass split for both QK^T and PV. Writes bf16 split output (ah/al).
// ---------------------------------------------------------------------------
#define AT_STAGE 32768
#define AT_SMEM  (16384 + 2 * AT_STAGE)

__global__ __launch_bounds__(128) void attn_mma(
    const __nv_bfloat16* __restrict__ qh, const __nv_bfloat16* __restrict__ ql,
    const __nv_bfloat16* __restrict__ kh, const __nv_bfloat16* __restrict__ kl,
    const __nv_bfloat16* __restrict__ vth, const __nv_bfloat16* __restrict__ vtl,
    __nv_bfloat16* __restrict__ ah, __nv_bfloat16* __restrict__ al)
{
    extern __shared__ char smem[];
    const uint32_t sb = smem_u32(smem);
    const int b = blockIdx.z, h = blockIdx.y;
    const int s0 = blockIdx.x * 64;
    const int tid = threadIdx.x, w = tid >> 5, lane = tid & 31;

    const uint32_t sQh = sb, sQl = sb + 8192;
    const uint32_t sStage = sb + 16384;

    auto loadKV = [&](int c, int buf) {
        uint32_t st = sStage + (uint32_t)buf * AT_STAGE;
        int j0 = c * 64;
#pragma unroll
        for (int it = 0; it < 4; it++) {
            int u = tid + it * 128;
            int r = u >> 3, cc = u & 7, cs = cc ^ (r & 7);
            size_t koff = (size_t)(j0 + r) * EE + h * DD + cc * 8;
            cp16(st + r * 128 + cs * 16, kh + koff);
            cp16(st + 8192 + r * 128 + cs * 16, kl + koff);
            size_t voff = (size_t)(h * DD + r) * MM + j0 + cc * 8;
            cp16(st + 16384 + r * 128 + cs * 16, vth + voff);
            cp16(st + 24576 + r * 128 + cs * 16, vtl + voff);
        }
    };

    // Q tiles + chunk 0 in group 0
    {
#pragma unroll
        for (int it = 0; it < 4; it++) {
            int u = tid + it * 128;
            int r = u >> 3, cc = u & 7, cs = cc ^ (r & 7);
            size_t off = ((size_t)(b * SS + s0 + r)) * EE + h * DD + cc * 8;
            cp16(sQh + r * 128 + cs * 16, qh + off);
            cp16(sQl + r * 128 + cs * 16, ql + off);
        }
        loadKV(0, 0);
        CP_COMMIT();
    }

    float m0 = -1e30f, m1 = -1e30f, l0 = 0.f, l1 = 0.f;
    float out[4][2][4];
#pragma unroll
    for (int g = 0; g < 4; g++)
#pragma unroll
        for (int s2 = 0; s2 < 2; s2++)
#pragma unroll
            for (int k = 0; k < 4; k++) out[g][s2][k] = 0.f;

    uint32_t qfh[4][4], qfl[4][4];

    for (int c = 0; c < 8; c++) {
        if (c < 7) {
            loadKV(c + 1, (c + 1) & 1);
            CP_COMMIT();
            CP_WAIT(1);
        } else {
            CP_WAIT(0);
        }
        __syncthreads();
        if (c == 0) {
#pragma unroll
            for (int kk = 0; kk < 4; kk++) {
                int r = w * 16 + (lane & 15);
                int cc = kk * 2 + (lane >> 4);
                int cs = cc ^ (r & 7);
                ldsm_x4(qfh[kk][0], qfh[kk][1], qfh[kk][2], qfh[kk][3], sQh + r * 128 + cs * 16);
                ldsm_x4(qfl[kk][0], qfl[kk][1], qfl[kk][2], qfl[kk][3], sQl + r * 128 + cs * 16);
            }
        }
        uint32_t stK = sStage + (uint32_t)(c & 1) * AT_STAGE;
        uint32_t stKl = stK + 8192, stVh = stK + 16384, stVl = stK + 24576;

        // ---- scores ----
        float sc[4][2][4];
#pragma unroll
        for (int g = 0; g < 4; g++)
#pragma unroll
            for (int s2 = 0; s2 < 2; s2++)
#pragma unroll
                for (int k = 0; k < 4; k++) sc[g][s2][k] = 0.f;

        const int rb_ = ((lane >> 4) << 3) + (lane & 7);
#pragma unroll
        for (int kk = 0; kk < 4; kk++) {
            const int ccb = kk * 2 + ((lane >> 3) & 1);
            uint32_t bk[4][4];
#pragma unroll
            for (int g = 0; g < 4; g++) {
                int r = g * 16 + rb_;
                int cs = ccb ^ (r & 7);
                ldsm_x4(bk[g][0], bk[g][1], bk[g][2], bk[g][3], stK + r * 128 + cs * 16);
            }
#pragma unroll
            for (int g = 0; g < 4; g++)
#pragma unroll
                for (int s2 = 0; s2 < 2; s2++) {
                    mma_16816(sc[g][s2], qfh[kk], bk[g][s2 * 2], bk[g][s2 * 2 + 1]);
                    mma_16816(sc[g][s2], qfl[kk], bk[g][s2 * 2], bk[g][s2 * 2 + 1]);
                }
#pragma unroll
            for (int g = 0; g < 4; g++) {
                int r = g * 16 + rb_;
                int cs = ccb ^ (r & 7);
                ldsm_x4(bk[g][0], bk[g][1], bk[g][2], bk[g][3], stKl + r * 128 + cs * 16);
            }
#pragma unroll
            for (int g = 0; g < 4; g++)
#pragma unroll
                for (int s2 = 0; s2 < 2; s2++)
                    mma_16816(sc[g][s2], qfh[kk], bk[g][s2 * 2], bk[g][s2 * 2 + 1]);
        }

        // ---- online softmax (rows r=lane>>2 and r+8; 4-thread groups) ----
        float rmax0 = -1e30f, rmax1 = -1e30f;
#pragma unroll
        for (int g = 0; g < 4; g++)
#pragma unroll
            for (int s2 = 0; s2 < 2; s2++) {
                rmax0 = fmaxf(rmax0, fmaxf(sc[g][s2][0], sc[g][s2][1]));
                rmax1 = fmaxf(rmax1, fmaxf(sc[g][s2][2], sc[g][s2][3]));
            }
        rmax0 = fmaxf(rmax0, __shfl_xor_sync(0xffffffffu, rmax0, 1));
        rmax0 = fmaxf(rmax0, __shfl_xor_sync(0xffffffffu, rmax0, 2));
        rmax1 = fmaxf(rmax1, __shfl_xor_sync(0xffffffffu, rmax1, 1));
        rmax1 = fmaxf(rmax1, __shfl_xor_sync(0xffffffffu, rmax1, 2));
        float nm0 = fmaxf(m0, rmax0), nm1 = fmaxf(m1, rmax1);
        float f0 = __expf(m0 - nm0), f1 = __expf(m1 - nm1);
        m0 = nm0; m1 = nm1;
        float ps0 = 0.f, ps1 = 0.f;
#pragma unroll
        for (int g = 0; g < 4; g++)
#pragma unroll
            for (int s2 = 0; s2 < 2; s2++) {
                sc[g][s2][0] = __expf(sc[g][s2][0] - m0);
                sc[g][s2][1] = __expf(sc[g][s2][1] - m0);
                sc[g][s2][2] = __expf(sc[g][s2][2] - m1);
                sc[g][s2][3] = __expf(sc[g][s2][3] - m1);
                ps0 += sc[g][s2][0] + sc[g][s2][1];
                ps1 += sc[g][s2][2] + sc[g][s2][3];
            }
        ps0 += __shfl_xor_sync(0xffffffffu, ps0, 1);
        ps0 += __shfl_xor_sync(0xffffffffu, ps0, 2);
        ps1 += __shfl_xor_sync(0xffffffffu, ps1, 1);
        ps1 += __shfl_xor_sync(0xffffffffu, ps1, 2);
        l0 = l0 * f0 + ps0;
        l1 = l1 * f1 + ps1;
#pragma unroll
        for (int g = 0; g < 4; g++)
#pragma unroll
            for (int s2 = 0; s2 < 2; s2++) {
                out[g][s2][0] *= f0; out[g][s2][1] *= f0;
                out[g][s2][2] *= f1; out[g][s2][3] *= f1;
            }

        // ---- PV ----
#pragma unroll
        for (int kk = 0; kk < 4; kk++) {
            uint32_t pah[4], pal[4];
            pah[0] = pack_bf2(sc[kk][0][0], sc[kk][0][1]);
            pah[1] = pack_bf2(sc[kk][0][2], sc[kk][0][3]);
            pah[2] = pack_bf2(sc[kk][1][0], sc[kk][1][1]);
            pah[3] = pack_bf2(sc[kk][1][2], sc[kk][1][3]);
            pal[0] = pack_bf2(bf_res(sc[kk][0][0]), bf_res(sc[kk][0][1]));
            pal[1] = pack_bf2(bf_res(sc[kk][0][2]), bf_res(sc[kk][0][3]));
            pal[2] = pack_bf2(bf_res(sc[kk][1][0]), bf_res(sc[kk][1][1]));
            pal[3] = pack_bf2(bf_res(sc[kk][1][2]), bf_res(sc[kk][1][3]));

            const int ccb = kk * 2 + ((lane >> 3) & 1);
            uint32_t bv[4][4];
#pragma unroll
            for (int g = 0; g < 4; g++) {
                int r = g * 16 + rb_;
                int cs = ccb ^ (r & 7);
                ldsm_x4(bv[g][0], bv[g][1], bv[g][2], bv[g][3], stVh + r * 128 + cs * 16);
            }
#pragma unroll
            for (int g = 0; g < 4; g++)
#pragma unroll
                for (int s2 = 0; s2 < 2; s2++) {
                    mma_16816(out[g][s2], pah, bv[g][s2 * 2], bv[g][s2 * 2 + 1]);
                    mma_16816(out[g][s2], pal, bv[g][s2 * 2], bv[g][s2 * 2 + 1]);
                }
#pragma unroll
            for (int g = 0; g < 4; g++) {
                int r = g * 16 + rb_;
                int cs = ccb ^ (r & 7);
                ldsm_x4(bv[g][0], bv[g][1], bv[g][2], bv[g][3], stVl + r * 128 + cs * 16);
            }
#pragma unroll
            for (int g = 0; g < 4; g++)
#pragma unroll
                for (int s2 = 0; s2 < 2; s2++)
                    mma_16816(out[g][s2], pah, bv[g][s2 * 2], bv[g][s2 * 2 + 1]);
        }
        __syncthreads();
    }

    // ---- epilogue: divide by l, write bf16 split ----
    float inv0 = 1.f / l0, inv1 = 1.f / l1;
    size_t row0 = (size_t)(b * SS) + s0 + w * 16 + (lane >> 2);
#pragma unroll
    for (int g = 0; g < 4; g++)
#pragma unroll
        for (int s2 = 0; s2 < 2; s2++) {
            int col = h * DD + g * 16 + s2 * 8 + (lane & 3) * 2;
            float v0 = out[g][s2][0] * inv0, v1 = out[g][s2][1] * inv0;
            float v2 = out[g][s2][2] * inv1, v3 = out[g][s2][3] * inv1;
            *(uint32_t*)(ah + row0 * EE + col)       = pack_bf2(v0, v1);
            *(uint32_t*)(ah + (row0 + 8) * EE + col) = pack_bf2(v2, v3);
            *(uint32_t*)(al + row0 * EE + col)       = pack_bf2(bf_res(v0), bf_res(v1));
            *(uint32_t*)(al + (row0 + 8) * EE + col) = pack_bf2(bf_res(v2), bf_res(v3));
        }
}

// ---------------------------------------------------------------------------
// Pointwise / reduction kernels
// ---------------------------------------------------------------------------
__device__ __forceinline__ void block_reduce2(float& s1, float& s2) {
    __shared__ float r1[8], r2[8];
    int lane = threadIdx.x & 31, w = threadIdx.x >> 5;
#pragma unroll
    for (int off = 16; off; off >>= 1) {
        s1 += __shfl_xor_sync(0xffffffffu, s1, off);
        s2 += __shfl_xor_sync(0xffffffffu, s2, off);
    }
    if (lane == 0) { r1[w] = s1; r2[w] = s2; }
    __syncthreads();
    if (w == 0) {
        s1 = (lane < 8) ? r1[lane] : 0.f;
        s2 = (lane < 8) ? r2[lane] : 0.f;
#pragma unroll
        for (int off = 4; off; off >>= 1) {
            s1 += __shfl_xor_sync(0xffffffffu, s1, off);
            s2 += __shfl_xor_sync(0xffffffffu, s2, off);
        }
        if (lane == 0) { r1[0] = s1; r2[0] = s2; }
    }
    __syncthreads();
    s1 = r1[0]; s2 = r2[0];
}

__global__ __launch_bounds__(256) void ln_kernel(
    const float* __restrict__ X, const float* __restrict__ g,
    const float* __restrict__ bta, float* __restrict__ out)
{
    size_t row = blockIdx.x;
    const float* x = X + row * EE;
    int c = threadIdx.x * 4;
    float4 v = *(const float4*)(x + c);
    float s1 = v.x + v.y + v.z + v.w;
    float s2 = v.x * v.x + v.y * v.y + v.z * v.z + v.w * v.w;
    block_reduce2(s1, s2);
    float mu = s1 * (1.f / EE);
    float var = s2 * (1.f / EE) - mu * mu;
    float rs = rsqrtf(var + 1e-5f);
    float4 gg = *(const float4*)(g + c);
    float4 bb = *(const float4*)(bta + c);
    float4 o;
    o.x = (v.x - mu) * rs * gg.x + bb.x;
    o.y = (v.y - mu) * rs * gg.y + bb.y;
    o.z = (v.z - mu) * rs * gg.z + bb.z;
    o.w = (v.w - mu) * rs * gg.w + bb.w;
    *(float4*)(out + row * EE + c) = o;
}

__global__ __launch_bounds__(256) void newmem_kernel(
    const float* __restrict__ gmemM,
    const float* __restrict__ gupd,
    const float* __restrict__ upd,
    const float* __restrict__ memv,
    const float* __restrict__ wg, const float* __restrict__ wb,
    float* __restrict__ out)
{
    int row = blockIdx.x;
    int b = row >> 9, m = row & 511;
    int c = threadIdx.x * 4;
    float4 gm = *(const float4*)(gmemM + (size_t)m * EE + c);
    float4 gu = *(const float4*)(gupd + (size_t)b * EE + c);
    float4 uv = *(const float4*)(upd + (size_t)b * EE + c);
    float4 mv = *(const float4*)(memv + (size_t)m * EE + c);
    float ge[4] = {gm.x + gu.x, gm.y + gu.y, gm.z + gu.z, gm.w + gu.w};
    float u[4] = {uv.x, uv.y, uv.z, uv.w};
    float mmv[4] = {mv.x, mv.y, mv.z, mv.w};
    float x[4];
    float s1 = 0.f, s2 = 0.f;
#pragma unroll
    for (int i = 0; i < 4; i++) {
        float gt = 1.f / (1.f + __expf(-ge[i]));
        x[i] = gt * u[i] + (1.f - gt) * mmv[i];
        s1 += x[i]; s2 += x[i] * x[i];
    }
    block_reduce2(s1, s2);
    float mu = s1 * (1.f / EE);
    float var = s2 * (1.f / EE) - mu * mu;
    float rs = rsqrtf(var + 1e-5f);
    float4 gg = *(const float4*)(wg + c);
    float4 bb = *(const float4*)(wb + c);
    float4 o;
    o.x = (x[0] - mu) * rs * gg.x + bb.x;
    o.y = (x[1] - mu) * rs * gg.y + bb.y;
    o.z = (x[2] - mu) * rs * gg.z + bb.z;
    o.w = (x[3] - mu) * rs * gg.w + bb.w;
    *(float4*)(out + (size_t)row * EE + c) = o;
}

__global__ __launch_bounds__(256) void mean_kernel(
    const float* __restrict__ q, float* __restrict__ wq)
{
    __shared__ float red[8][33];
    int b = blockIdx.y;
    int e0 = blockIdx.x * 32;
    int el = threadIdx.x & 31, strip = threadIdx.x >> 5;
    const float* p = q + ((size_t)b * SS + strip * 256) * EE + e0 + el;
    float s = 0.f;
#pragma unroll 4
    for (int i = 0; i < 256; i++) s += p[(size_t)i * EE];
    red[strip][el] = s;
    __syncthreads();
    if (strip == 0) {
        float t = 0.f;
#pragma unroll
        for (int k = 0; k < 8; k++) t += red[k][el];
        wq[(size_t)b * EE + e0 + el] = t * (1.f / SS);
    }
}

__global__ __launch_bounds__(256) void gemv8(
    const float* __restrict__ A,
    const float* __restrict__ B, int ldb,
    const float* __restrict__ bias,
    float* __restrict__ C, int N, int K)
{
    int w = threadIdx.x >> 5, lane = threadIdx.x & 31;
    int n = blockIdx.x * 8 + w;
    if (n >= N) return;
    const float* brow = B + (size_t)n * ldb;
    for (int b = 0; b < BB; b++) {
        const float* arow = A + (size_t)b * K;
        float s = 0.f;
        for (int i = lane; i < K; i += 32) s += arow[i] * brow[i];
#pragma unroll
        for (int off = 16; off; off >>= 1) s += __shfl_xor_sync(0xffffffffu, s, off);
        if (lane == 0) C[(size_t)b * N + n] = s + (bias ? bias[n] : 0.f);
    }
}

// ---------------------------------------------------------------------------
extern "C" void kernel_launch(void* const* d_in, const int* in_sizes, int n_in,
                              void* d_out, int out_size)
{
    (void)in_sizes; (void)n_in; (void)out_size;
    const float* query   = (const float*)d_in[0];
    const float* memory  = (const float*)d_in[1];
    const float* r_in_w  = (const float*)d_in[2];
    const float* r_in_b  = (const float*)d_in[3];
    const float* r_out_w = (const float*)d_in[4];
    const float* r_out_b = (const float*)d_in[5];
    const float* w_in_w  = (const float*)d_in[6];
    const float* w_in_b  = (const float*)d_in[7];
    const float* w_out_w = (const float*)d_in[8];
    const float* w_out_b = (const float*)d_in[9];
    const float* rn_g    = (const float*)d_in[10];
    const float* rn_b    = (const float*)d_in[11];
    const float* wn_g    = (const float*)d_in[12];
    const float* wn_b    = (const float*)d_in[13];
    const float* gate_w  = (const float*)d_in[14];
    const float* gate_b  = (const float*)d_in[15];
    float* out = (float*)d_out;

    float *KV, *y, *wq, *vw, *upd, *gmem, *gupd;
    cudaGetSymbolAddress((void**)&KV,   g_KV);
    cudaGetSymbolAddress((void**)&y,    g_y);
    cudaGetSymbolAddress((void**)&wq,   g_wq);
    cudaGetSymbolAddress((void**)&vw,   g_vw);
    cudaGetSymbolAddress((void**)&upd,  g_upd);
    cudaGetSymbolAddress((void**)&gmem, g_gmem);
    cudaGetSymbolAddress((void**)&gupd, g_gupd);

    __nv_bfloat16 *qh, *ql, *qph, *qpl, *ahp, *alp, *mh, *ml, *kh, *kl, *vth, *vtl;
    __nv_bfloat16 *riwh, *riwl, *rowh, *rowl, *gwh, *gwl;
    cudaGetSymbolAddress((void**)&qh,   g_qh);
    cudaGetSymbolAddress((void**)&ql,   g_ql);
    cudaGetSymbolAddress((void**)&qph,  g_qph);
    cudaGetSymbolAddress((void**)&qpl,  g_qpl);
    cudaGetSymbolAddress((void**)&ahp,  g_ah);
    cudaGetSymbolAddress((void**)&alp,  g_al);
    cudaGetSymbolAddress((void**)&mh,   g_mh);
    cudaGetSymbolAddress((void**)&ml,   g_ml);
    cudaGetSymbolAddress((void**)&kh,   g_kh);
    cudaGetSymbolAddress((void**)&kl,   g_kl);
    cudaGetSymbolAddress((void**)&vth,  g_vth);
    cudaGetSymbolAddress((void**)&vtl,  g_vtl);
    cudaGetSymbolAddress((void**)&riwh, g_riwh);
    cudaGetSymbolAddress((void**)&riwl, g_riwl);
    cudaGetSymbolAddress((void**)&rowh, g_rowh);
    cudaGetSymbolAddress((void**)&rowl, g_rowl);
    cudaGetSymbolAddress((void**)&gwh,  g_gwh);
    cudaGetSymbolAddress((void**)&gwl,  g_gwl);

    cudaFuncSetAttribute(gemm_mma, cudaFuncAttributeMaxDynamicSharedMemorySize, GSMEM);
    cudaFuncSetAttribute(attn_mma, cudaFuncAttributeMaxDynamicSharedMemorySize, AT_SMEM);

    // --- split conversions (inputs + weights) ---
    cvt_split<<<3 * EE * EE / 1024, 256>>>(r_in_w, riwh, riwl, 3 * EE * EE);
    cvt_split<<<EE * EE / 1024, 256>>>(r_out_w, rowh, rowl, EE * EE);
    cvt_split<<<2 * EE * EE / 1024, 256>>>(gate_w, gwh, gwl, 2 * EE * EE);
    cvt_split<<<MM * EE / 1024, 256>>>(memory, mh, ml, MM * EE);
    cvt_split<<<BB * SS * EE / 1024, 256>>>(query, qh, ql, BB * SS * EE);

    // --- r-branch ---
    // KV projection (shared across batch): (512 x 2048) fp32
    gemm_mma<<<dim3(2 * EE / 128, MM / 128), 256, GSMEM>>>(
        mh, ml, EE, riwh + (size_t)EE * EE, riwl + (size_t)EE * EE, EE,
        r_in_b + EE, nullptr, KV, nullptr, nullptr, 2 * EE, 1.f);
    // K split + V transposed split for attention
    split_k<<<MM, 256>>>(KV, kh, kl);
    transpose_v<<<dim3(EE / 32, MM / 32), 256>>>(KV, vth, vtl);
    // Q projection, prescaled by 1/sqrt(D), direct bf16 split output
    gemm_mma<<<dim3(EE / 128, BB * SS / 128), 256, GSMEM>>>(
        qh, ql, EE, riwh, riwl, EE,
        r_in_b, nullptr, nullptr, qph, qpl, EE, 0.125f);
    // attention (HMMA, split precision), writes ah/al split directly
    attn_mma<<<dim3(SS / 64, HH, BB), 128, AT_SMEM>>>(
        qph, qpl, kh, kl, vth, vtl, ahp, alp);
    // out projection + residual + LN
    gemm_mma<<<dim3(EE / 128, BB * SS / 128), 256, GSMEM>>>(
        ahp, alp, EE, rowh, rowl, EE,
        r_out_b, query, y, nullptr, nullptr, EE, 1.f);
    ln_kernel<<<BB * SS, 256>>>(y, rn_g, rn_b, out);

    // --- w-branch (collapsed) ---
    mean_kernel<<<dim3(EE / 32, BB), 256>>>(query, wq);
    gemv8<<<EE / 8, 256>>>(wq, w_in_w + (size_t)2 * EE * EE, EE, w_in_b + 2 * EE, vw, EE, EE);
    gemv8<<<EE / 8, 256>>>(vw, w_out_w, EE, w_out_b, upd, EE, EE);

    // --- gate (decomposed) ---
    gemm_mma<<<dim3(EE / 128, MM / 128), 256, GSMEM>>>(
        mh, ml, EE, gwh, gwl, 2 * EE,
        gate_b, nullptr, gmem, nullptr, nullptr, EE, 1.f);
    gemv8<<<EE / 8, 256>>>(upd, gate_w + EE, 2 * EE, nullptr, gupd, EE, EE);

    newmem_kernel<<<BB * MM, 256>>>(gmem, gupd, upd, memory, wn_g, wn_b,
                                    out + (size_t)BB * SS * EE);
}

// round 8
// speedup vs baseline: 3.2096x; 1.3630x over previous
#include <cuda_runtime.h>
#include <cuda_bf16.h>
#include <math.h>
#include <stdint.h>

// ---------------------------------------------------------------------------
// Problem constants
// ---------------------------------------------------------------------------
#define BB 8
#define SS 2048
#define MM 512
#define EE 1024
#define HH 16
#define DD 64

// ---------------------------------------------------------------------------
// Scratch (device globals; no allocation allowed)
// ---------------------------------------------------------------------------
__device__ float g_KV[MM * 2 * EE];
__device__ float g_y[BB * SS * EE];
__device__ float g_wq[BB * EE];
__device__ float g_vw[BB * EE];
__device__ float g_upd[BB * EE];
__device__ float g_gmem[MM * EE];
__device__ float g_gupd[BB * EE];

// bf16 hi/lo split buffers
__device__ __nv_bfloat16 g_qh[BB * SS * EE];
__device__ __nv_bfloat16 g_ql[BB * SS * EE];
__device__ __nv_bfloat16 g_qph[BB * SS * EE];
__device__ __nv_bfloat16 g_qpl[BB * SS * EE];
__device__ __nv_bfloat16 g_ah[BB * SS * EE];
__device__ __nv_bfloat16 g_al[BB * SS * EE];
__device__ __nv_bfloat16 g_mh[MM * EE];
__device__ __nv_bfloat16 g_ml[MM * EE];
__device__ __nv_bfloat16 g_kh[MM * EE];
__device__ __nv_bfloat16 g_kl[MM * EE];
__device__ __nv_bfloat16 g_vth[EE * MM];
__device__ __nv_bfloat16 g_vtl[EE * MM];
__device__ __nv_bfloat16 g_riwh[3 * EE * EE];
__device__ __nv_bfloat16 g_riwl[3 * EE * EE];
__device__ __nv_bfloat16 g_rowh[EE * EE];
__device__ __nv_bfloat16 g_rowl[EE * EE];
__device__ __nv_bfloat16 g_gwh[EE * 2 * EE];
__device__ __nv_bfloat16 g_gwl[EE * 2 * EE];

// ---------------------------------------------------------------------------
// PTX helpers
// ---------------------------------------------------------------------------
__device__ __forceinline__ uint32_t smem_u32(const void* p) {
    uint32_t a;
    asm("{ .reg .u64 t; cvta.to.shared.u64 t, %1; cvt.u32.u64 %0, t; }" : "=r"(a) : "l"(p));
    return a;
}

#define CP_COMMIT() asm volatile("cp.async.commit_group;" ::: "memory")
#define CP_WAIT(n)  asm volatile("cp.async.wait_group %0;" :: "n"(n) : "memory")

__device__ __forceinline__ void cp16(uint32_t saddr, const void* g) {
    asm volatile("cp.async.cg.shared.global [%0], [%1], 16;" :: "r"(saddr), "l"(g) : "memory");
}

__device__ __forceinline__ void ldsm_x4(uint32_t& r0, uint32_t& r1, uint32_t& r2,
                                        uint32_t& r3, uint32_t addr) {
    asm volatile("ldmatrix.sync.aligned.m8n8.x4.shared.b16 {%0,%1,%2,%3}, [%4];"
                 : "=r"(r0), "=r"(r1), "=r"(r2), "=r"(r3) : "r"(addr));
}

__device__ __forceinline__ void mma_16816(float* d, const uint32_t* a,
                                          uint32_t b0, uint32_t b1) {
    asm volatile(
        "mma.sync.aligned.m16n8k16.row.col.f32.bf16.bf16.f32 "
        "{%0,%1,%2,%3}, {%4,%5,%6,%7}, {%8,%9}, {%0,%1,%2,%3};"
        : "+f"(d[0]), "+f"(d[1]), "+f"(d[2]), "+f"(d[3])
        : "r"(a[0]), "r"(a[1]), "r"(a[2]), "r"(a[3]), "r"(b0), "r"(b1));
}

__device__ __forceinline__ uint32_t pack_bf2(float a, float b) {
    __nv_bfloat162 t = __floats2bfloat162_rn(a, b);
    return *reinterpret_cast<uint32_t*>(&t);
}
__device__ __forceinline__ float bf_res(float x) {
    return x - __bfloat162float(__float2bfloat16_rn(x));
}

// ---------------------------------------------------------------------------
// hi/lo bf16 split conversion
// ---------------------------------------------------------------------------
__global__ __launch_bounds__(256) void cvt_split(
    const float* __restrict__ x, __nv_bfloat16* __restrict__ hi,
    __nv_bfloat16* __restrict__ lo, int n)
{
    int i = (blockIdx.x * 256 + threadIdx.x) * 4;
    if (i >= n) return;
    float4 v = *(const float4*)(x + i);
    __nv_bfloat16 h0 = __float2bfloat16_rn(v.x);
    __nv_bfloat16 h1 = __float2bfloat16_rn(v.y);
    __nv_bfloat16 h2 = __float2bfloat16_rn(v.z);
    __nv_bfloat16 h3 = __float2bfloat16_rn(v.w);
    *(__nv_bfloat162*)(hi + i)     = __halves2bfloat162(h0, h1);
    *(__nv_bfloat162*)(hi + i + 2) = __halves2bfloat162(h2, h3);
    *(__nv_bfloat162*)(lo + i)     = __halves2bfloat162(
        __float2bfloat16_rn(v.x - __bfloat162float(h0)),
        __float2bfloat16_rn(v.y - __bfloat162float(h1)));
    *(__nv_bfloat162*)(lo + i + 2) = __halves2bfloat162(
        __float2bfloat16_rn(v.z - __bfloat162float(h2)),
        __float2bfloat16_rn(v.w - __bfloat162float(h3)));
}

// ---------------------------------------------------------------------------
// KV prep
// ---------------------------------------------------------------------------
__global__ __launch_bounds__(256) void split_k(
    const float* __restrict__ KV, __nv_bfloat16* __restrict__ kh,
    __nv_bfloat16* __restrict__ kl)
{
    int j = blockIdx.x;
    int c = threadIdx.x * 4;
    float4 v = *(const float4*)(KV + (size_t)j * (2 * EE) + c);
    __nv_bfloat16 h0 = __float2bfloat16_rn(v.x);
    __nv_bfloat16 h1 = __float2bfloat16_rn(v.y);
    __nv_bfloat16 h2 = __float2bfloat16_rn(v.z);
    __nv_bfloat16 h3 = __float2bfloat16_rn(v.w);
    size_t o = (size_t)j * EE + c;
    *(__nv_bfloat162*)(kh + o)     = __halves2bfloat162(h0, h1);
    *(__nv_bfloat162*)(kh + o + 2) = __halves2bfloat162(h2, h3);
    *(__nv_bfloat162*)(kl + o)     = __halves2bfloat162(
        __float2bfloat16_rn(v.x - __bfloat162float(h0)),
        __float2bfloat16_rn(v.y - __bfloat162float(h1)));
    *(__nv_bfloat162*)(kl + o + 2) = __halves2bfloat162(
        __float2bfloat16_rn(v.z - __bfloat162float(h2)),
        __float2bfloat16_rn(v.w - __bfloat162float(h3)));
}

__global__ __launch_bounds__(256) void transpose_v(
    const float* __restrict__ KV, __nv_bfloat16* __restrict__ vth,
    __nv_bfloat16* __restrict__ vtl)
{
    __shared__ float t[32][33];
    int e0 = blockIdx.x * 32, j0 = blockIdx.y * 32;
    int tx = threadIdx.x & 31, ty = threadIdx.x >> 5;
#pragma unroll
    for (int k2 = 0; k2 < 4; k2++)
        t[ty + k2 * 8][tx] = KV[(size_t)(j0 + ty + k2 * 8) * (2 * EE) + EE + e0 + tx];
    __syncthreads();
#pragma unroll
    for (int k2 = 0; k2 < 4; k2++) {
        float v = t[tx][ty + k2 * 8];
        __nv_bfloat16 hv = __float2bfloat16_rn(v);
        size_t o = (size_t)(e0 + ty + k2 * 8) * MM + j0 + tx;
        vth[o] = hv;
        vtl[o] = __float2bfloat16_rn(v - __bfloat162float(hv));
    }
}

// ---------------------------------------------------------------------------
// HMMA split-bf16 GEMM (NT), FUSED 3-pass:
// per K-chunk load Ah,Al,Bh,Bl once, issue Ah*Bh + Al*Bh + Ah*Bl.
// Tile 128x128, BK=32, 3 stages x 32KB, 2 CTAs/SM.
// ---------------------------------------------------------------------------
#define GSTAGE 32768
#define GSMEM  (3 * GSTAGE)

__global__ __launch_bounds__(256, 2) void gemm_mma(
    const __nv_bfloat16* __restrict__ Ah, const __nv_bfloat16* __restrict__ Al, int lda,
    const __nv_bfloat16* __restrict__ Bh, const __nv_bfloat16* __restrict__ Bl, int ldb,
    const float* __restrict__ bias, const float* __restrict__ res,
    float* __restrict__ C,
    __nv_bfloat16* __restrict__ Chi, __nv_bfloat16* __restrict__ Clo,
    int N, float scale)
{
    extern __shared__ char smem[];
    const uint32_t sbase = smem_u32(smem);
    const int tid = threadIdx.x;
    const int wid = tid >> 5, lane = tid & 31;
    const int wm = wid >> 2, wn = wid & 3;
    const int mbase = blockIdx.y * 128;
    const int nbase = blockIdx.x * 128;

    float acc[4][4][4];
#pragma unroll
    for (int i = 0; i < 4; i++)
#pragma unroll
        for (int j = 0; j < 4; j++)
#pragma unroll
            for (int k = 0; k < 4; k++) acc[i][j][k] = 0.f;

    // stage layout: Ah @0, Al @8192, Bh @16384, Bl @24576  (each 128x32 bf16)
    auto load_stage = [&](int kt, int buf) {
        uint32_t st = sbase + (uint32_t)buf * GSTAGE;
#pragma unroll
        for (int j = 0; j < 2; j++) {
            int u = tid + j * 256;
            int r = u >> 2, c = u & 3;
            int cs = c ^ ((r >> 1) & 3);
            uint32_t dst = st + r * 64 + cs * 16;
            size_t aoff = (size_t)(mbase + r) * lda + kt * 32 + c * 8;
            size_t boff = (size_t)(nbase + r) * ldb + kt * 32 + c * 8;
            cp16(dst, Ah + aoff);
            cp16(dst + 8192, Al + aoff);
            cp16(dst + 16384, Bh + boff);
            cp16(dst + 24576, Bl + boff);
        }
    };

    const int NCH = 32;   // 1024 / 32
    load_stage(0, 0); CP_COMMIT();
    load_stage(1, 1); CP_COMMIT();

    for (int s = 0; s < NCH; ++s) {
        int pf = s + 2;
        if (pf < NCH) {
            load_stage(pf, pf % 3);
            CP_COMMIT();
            CP_WAIT(2);
        } else {
            CP_WAIT(0);
        }
        __syncthreads();

        uint32_t st = sbase + (uint32_t)(s % 3) * GSTAGE;

#pragma unroll
        for (int kk = 0; kk < 2; kk++) {
            uint32_t ah_f[4][4], al_f[4][4], b_f[2][4];
            // A-hi fragments
#pragma unroll
            for (int mi = 0; mi < 4; mi++) {
                int r = wm * 64 + mi * 16 + (lane & 15);
                int c = kk * 2 + (lane >> 4);
                int cs = c ^ ((r >> 1) & 3);
                ldsm_x4(ah_f[mi][0], ah_f[mi][1], ah_f[mi][2], ah_f[mi][3],
                        st + r * 64 + cs * 16);
            }
            // B-hi fragments
#pragma unroll
            for (int nb = 0; nb < 2; nb++) {
                int r = wn * 32 + nb * 16 + ((lane >> 4) << 3) + (lane & 7);
                int c = kk * 2 + ((lane >> 3) & 1);
                int cs = c ^ ((r >> 1) & 3);
                ldsm_x4(b_f[nb][0], b_f[nb][1], b_f[nb][2], b_f[nb][3],
                        st + 16384 + r * 64 + cs * 16);
            }
            // Ah * Bh
#pragma unroll
            for (int mi = 0; mi < 4; mi++)
#pragma unroll
                for (int ni = 0; ni < 4; ni++) {
                    int nb = ni >> 1, hh = ni & 1;
                    mma_16816(acc[mi][ni], ah_f[mi], b_f[nb][hh * 2], b_f[nb][hh * 2 + 1]);
                }
            // A-lo fragments
#pragma unroll
            for (int mi = 0; mi < 4; mi++) {
                int r = wm * 64 + mi * 16 + (lane & 15);
                int c = kk * 2 + (lane >> 4);
                int cs = c ^ ((r >> 1) & 3);
                ldsm_x4(al_f[mi][0], al_f[mi][1], al_f[mi][2], al_f[mi][3],
                        st + 8192 + r * 64 + cs * 16);
            }
            // Al * Bh
#pragma unroll
            for (int mi = 0; mi < 4; mi++)
#pragma unroll
                for (int ni = 0; ni < 4; ni++) {
                    int nb = ni >> 1, hh = ni & 1;
                    mma_16816(acc[mi][ni], al_f[mi], b_f[nb][hh * 2], b_f[nb][hh * 2 + 1]);
                }
            // B-lo fragments (overwrite b_f)
#pragma unroll
            for (int nb = 0; nb < 2; nb++) {
                int r = wn * 32 + nb * 16 + ((lane >> 4) << 3) + (lane & 7);
                int c = kk * 2 + ((lane >> 3) & 1);
                int cs = c ^ ((r >> 1) & 3);
                ldsm_x4(b_f[nb][0], b_f[nb][1], b_f[nb][2], b_f[nb][3],
                        st + 24576 + r * 64 + cs * 16);
            }
            // Ah * Bl
#pragma unroll
            for (int mi = 0; mi < 4; mi++)
#pragma unroll
                for (int ni = 0; ni < 4; ni++) {
                    int nb = ni >> 1, hh = ni & 1;
                    mma_16816(acc[mi][ni], ah_f[mi], b_f[nb][hh * 2], b_f[nb][hh * 2 + 1]);
                }
        }
        __syncthreads();
    }

    // ---- epilogue ----
    const int r_lo = lane >> 2;
    const int c_off = (lane & 3) * 2;
#pragma unroll
    for (int mi = 0; mi < 4; mi++) {
        size_t row = (size_t)mbase + wm * 64 + mi * 16 + r_lo;
#pragma unroll
        for (int ni = 0; ni < 4; ni++) {
            int col = nbase + wn * 32 + ni * 8 + c_off;
            const float* a4 = acc[mi][ni];
            float2 bv = *(const float2*)(bias + col);
            float2 v0, v1;
            v0.x = scale * (a4[0] + bv.x); v0.y = scale * (a4[1] + bv.y);
            v1.x = scale * (a4[2] + bv.x); v1.y = scale * (a4[3] + bv.y);
            if (Chi) {
                *(uint32_t*)(Chi + row * N + col)       = pack_bf2(v0.x, v0.y);
                *(uint32_t*)(Chi + (row + 8) * N + col) = pack_bf2(v1.x, v1.y);
                *(uint32_t*)(Clo + row * N + col)       = pack_bf2(bf_res(v0.x), bf_res(v0.y));
                *(uint32_t*)(Clo + (row + 8) * N + col) = pack_bf2(bf_res(v1.x), bf_res(v1.y));
            } else {
                if (res) {
                    float2 r0 = *(const float2*)(res + row * N + col);
                    float2 r1 = *(const float2*)(res + (row + 8) * N + col);
                    v0.x += r0.x; v0.y += r0.y; v1.x += r1.x; v1.y += r1.y;
                }
                *(float2*)(C + row * N + col) = v0;
                *(float2*)(C + (row + 8) * N + col) = v1;
            }
        }
    }
}

// ---------------------------------------------------------------------------
// HMMA flash attention (unchanged math; 2 CTAs/SM enforced)
// ---------------------------------------------------------------------------
#define AT_STAGE 32768
#define AT_SMEM  (16384 + 2 * AT_STAGE)

__global__ __launch_bounds__(128, 2) void attn_mma(
    const __nv_bfloat16* __restrict__ qh, const __nv_bfloat16* __restrict__ ql,
    const __nv_bfloat16* __restrict__ kh, const __nv_bfloat16* __restrict__ kl,
    const __nv_bfloat16* __restrict__ vth, const __nv_bfloat16* __restrict__ vtl,
    __nv_bfloat16* __restrict__ ah, __nv_bfloat16* __restrict__ al)
{
    extern __shared__ char smem[];
    const uint32_t sb = smem_u32(smem);
    const int b = blockIdx.z, h = blockIdx.y;
    const int s0 = blockIdx.x * 64;
    const int tid = threadIdx.x, w = tid >> 5, lane = tid & 31;

    const uint32_t sQh = sb, sQl = sb + 8192;
    const uint32_t sStage = sb + 16384;

    auto loadKV = [&](int c, int buf) {
        uint32_t st = sStage + (uint32_t)buf * AT_STAGE;
        int j0 = c * 64;
#pragma unroll
        for (int it = 0; it < 4; it++) {
            int u = tid + it * 128;
            int r = u >> 3, cc = u & 7, cs = cc ^ (r & 7);
            size_t koff = (size_t)(j0 + r) * EE + h * DD + cc * 8;
            cp16(st + r * 128 + cs * 16, kh + koff);
            cp16(st + 8192 + r * 128 + cs * 16, kl + koff);
            size_t voff = (size_t)(h * DD + r) * MM + j0 + cc * 8;
            cp16(st + 16384 + r * 128 + cs * 16, vth + voff);
            cp16(st + 24576 + r * 128 + cs * 16, vtl + voff);
        }
    };

    {
#pragma unroll
        for (int it = 0; it < 4; it++) {
            int u = tid + it * 128;
            int r = u >> 3, cc = u & 7, cs = cc ^ (r & 7);
            size_t off = ((size_t)(b * SS + s0 + r)) * EE + h * DD + cc * 8;
            cp16(sQh + r * 128 + cs * 16, qh + off);
            cp16(sQl + r * 128 + cs * 16, ql + off);
        }
        loadKV(0, 0);
        CP_COMMIT();
    }

    float m0 = -1e30f, m1 = -1e30f, l0 = 0.f, l1 = 0.f;
    float out[4][2][4];
#pragma unroll
    for (int g = 0; g < 4; g++)
#pragma unroll
        for (int s2 = 0; s2 < 2; s2++)
#pragma unroll
            for (int k = 0; k < 4; k++) out[g][s2][k] = 0.f;

    uint32_t qfh[4][4], qfl[4][4];

    for (int c = 0; c < 8; c++) {
        if (c < 7) {
            loadKV(c + 1, (c + 1) & 1);
            CP_COMMIT();
            CP_WAIT(1);
        } else {
            CP_WAIT(0);
        }
        __syncthreads();
        if (c == 0) {
#pragma unroll
            for (int kk = 0; kk < 4; kk++) {
                int r = w * 16 + (lane & 15);
                int cc = kk * 2 + (lane >> 4);
                int cs = cc ^ (r & 7);
                ldsm_x4(qfh[kk][0], qfh[kk][1], qfh[kk][2], qfh[kk][3], sQh + r * 128 + cs * 16);
                ldsm_x4(qfl[kk][0], qfl[kk][1], qfl[kk][2], qfl[kk][3], sQl + r * 128 + cs * 16);
            }
        }
        uint32_t stK = sStage + (uint32_t)(c & 1) * AT_STAGE;
        uint32_t stKl = stK + 8192, stVh = stK + 16384, stVl = stK + 24576;

        float sc[4][2][4];
#pragma unroll
        for (int g = 0; g < 4; g++)
#pragma unroll
            for (int s2 = 0; s2 < 2; s2++)
#pragma unroll
                for (int k = 0; k < 4; k++) sc[g][s2][k] = 0.f;

        const int rb_ = ((lane >> 4) << 3) + (lane & 7);
#pragma unroll
        for (int kk = 0; kk < 4; kk++) {
            const int ccb = kk * 2 + ((lane >> 3) & 1);
            uint32_t bk[4][4];
#pragma unroll
            for (int g = 0; g < 4; g++) {
                int r = g * 16 + rb_;
                int cs = ccb ^ (r & 7);
                ldsm_x4(bk[g][0], bk[g][1], bk[g][2], bk[g][3], stK + r * 128 + cs * 16);
            }
#pragma unroll
            for (int g = 0; g < 4; g++)
#pragma unroll
                for (int s2 = 0; s2 < 2; s2++) {
                    mma_16816(sc[g][s2], qfh[kk], bk[g][s2 * 2], bk[g][s2 * 2 + 1]);
                    mma_16816(sc[g][s2], qfl[kk], bk[g][s2 * 2], bk[g][s2 * 2 + 1]);
                }
#pragma unroll
            for (int g = 0; g < 4; g++) {
                int r = g * 16 + rb_;
                int cs = ccb ^ (r & 7);
                ldsm_x4(bk[g][0], bk[g][1], bk[g][2], bk[g][3], stKl + r * 128 + cs * 16);
            }
#pragma unroll
            for (int g = 0; g < 4; g++)
#pragma unroll
                for (int s2 = 0; s2 < 2; s2++)
                    mma_16816(sc[g][s2], qfh[kk], bk[g][s2 * 2], bk[g][s2 * 2 + 1]);
        }

        float rmax0 = -1e30f, rmax1 = -1e30f;
#pragma unroll
        for (int g = 0; g < 4; g++)
#pragma unroll
            for (int s2 = 0; s2 < 2; s2++) {
                rmax0 = fmaxf(rmax0, fmaxf(sc[g][s2][0], sc[g][s2][1]));
                rmax1 = fmaxf(rmax1, fmaxf(sc[g][s2][2], sc[g][s2][3]));
            }
        rmax0 = fmaxf(rmax0, __shfl_xor_sync(0xffffffffu, rmax0, 1));
        rmax0 = fmaxf(rmax0, __shfl_xor_sync(0xffffffffu, rmax0, 2));
        rmax1 = fmaxf(rmax1, __shfl_xor_sync(0xffffffffu, rmax1, 1));
        rmax1 = fmaxf(rmax1, __shfl_xor_sync(0xffffffffu, rmax1, 2));
        float nm0 = fmaxf(m0, rmax0), nm1 = fmaxf(m1, rmax1);
        float f0 = __expf(m0 - nm0), f1 = __expf(m1 - nm1);
        m0 = nm0; m1 = nm1;
        float ps0 = 0.f, ps1 = 0.f;
#pragma unroll
        for (int g = 0; g < 4; g++)
#pragma unroll
            for (int s2 = 0; s2 < 2; s2++) {
                sc[g][s2][0] = __expf(sc[g][s2][0] - m0);
                sc[g][s2][1] = __expf(sc[g][s2][1] - m0);
                sc[g][s2][2] = __expf(sc[g][s2][2] - m1);
                sc[g][s2][3] = __expf(sc[g][s2][3] - m1);
                ps0 += sc[g][s2][0] + sc[g][s2][1];
                ps1 += sc[g][s2][2] + sc[g][s2][3];
            }
        ps0 += __shfl_xor_sync(0xffffffffu, ps0, 1);
        ps0 += __shfl_xor_sync(0xffffffffu, ps0, 2);
        ps1 += __shfl_xor_sync(0xffffffffu, ps1, 1);
        ps1 += __shfl_xor_sync(0xffffffffu, ps1, 2);
        l0 = l0 * f0 + ps0;
        l1 = l1 * f1 + ps1;
#pragma unroll
        for (int g = 0; g < 4; g++)
#pragma unroll
            for (int s2 = 0; s2 < 2; s2++) {
                out[g][s2][0] *= f0; out[g][s2][1] *= f0;
                out[g][s2][2] *= f1; out[g][s2][3] *= f1;
            }

#pragma unroll
        for (int kk = 0; kk < 4; kk++) {
            uint32_t pah[4], pal[4];
            pah[0] = pack_bf2(sc[kk][0][0], sc[kk][0][1]);
            pah[1] = pack_bf2(sc[kk][0][2], sc[kk][0][3]);
            pah[2] = pack_bf2(sc[kk][1][0], sc[kk][1][1]);
            pah[3] = pack_bf2(sc[kk][1][2], sc[kk][1][3]);
            pal[0] = pack_bf2(bf_res(sc[kk][0][0]), bf_res(sc[kk][0][1]));
            pal[1] = pack_bf2(bf_res(sc[kk][0][2]), bf_res(sc[kk][0][3]));
            pal[2] = pack_bf2(bf_res(sc[kk][1][0]), bf_res(sc[kk][1][1]));
            pal[3] = pack_bf2(bf_res(sc[kk][1][2]), bf_res(sc[kk][1][3]));

            const int ccb = kk * 2 + ((lane >> 3) & 1);
            uint32_t bv[4][4];
#pragma unroll
            for (int g = 0; g < 4; g++) {
                int r = g * 16 + rb_;
                int cs = ccb ^ (r & 7);
                ldsm_x4(bv[g][0], bv[g][1], bv[g][2], bv[g][3], stVh + r * 128 + cs * 16);
            }
#pragma unroll
            for (int g = 0; g < 4; g++)
#pragma unroll
                for (int s2 = 0; s2 < 2; s2++) {
                    mma_16816(out[g][s2], pah, bv[g][s2 * 2], bv[g][s2 * 2 + 1]);
                    mma_16816(out[g][s2], pal, bv[g][s2 * 2], bv[g][s2 * 2 + 1]);
                }
#pragma unroll
            for (int g = 0; g < 4; g++) {
                int r = g * 16 + rb_;
                int cs = ccb ^ (r & 7);
                ldsm_x4(bv[g][0], bv[g][1], bv[g][2], bv[g][3], stVl + r * 128 + cs * 16);
            }
#pragma unroll
            for (int g = 0; g < 4; g++)
#pragma unroll
                for (int s2 = 0; s2 < 2; s2++)
                    mma_16816(out[g][s2], pah, bv[g][s2 * 2], bv[g][s2 * 2 + 1]);
        }
        __syncthreads();
    }

    float inv0 = 1.f / l0, inv1 = 1.f / l1;
    size_t row0 = (size_t)(b * SS) + s0 + w * 16 + (lane >> 2);
#pragma unroll
    for (int g = 0; g < 4; g++)
#pragma unroll
        for (int s2 = 0; s2 < 2; s2++) {
            int col = h * DD + g * 16 + s2 * 8 + (lane & 3) * 2;
            float v0 = out[g][s2][0] * inv0, v1 = out[g][s2][1] * inv0;
            float v2 = out[g][s2][2] * inv1, v3 = out[g][s2][3] * inv1;
            *(uint32_t*)(ah + row0 * EE + col)       = pack_bf2(v0, v1);
            *(uint32_t*)(ah + (row0 + 8) * EE + col) = pack_bf2(v2, v3);
            *(uint32_t*)(al + row0 * EE + col)       = pack_bf2(bf_res(v0), bf_res(v1));
            *(uint32_t*)(al + (row0 + 8) * EE + col) = pack_bf2(bf_res(v2), bf_res(v3));
        }
}

// ---------------------------------------------------------------------------
// Pointwise / reduction kernels
// ---------------------------------------------------------------------------
__device__ __forceinline__ void block_reduce2(float& s1, float& s2) {
    __shared__ float r1[8], r2[8];
    int lane = threadIdx.x & 31, w = threadIdx.x >> 5;
#pragma unroll
    for (int off = 16; off; off >>= 1) {
        s1 += __shfl_xor_sync(0xffffffffu, s1, off);
        s2 += __shfl_xor_sync(0xffffffffu, s2, off);
    }
    if (lane == 0) { r1[w] = s1; r2[w] = s2; }
    __syncthreads();
    if (w == 0) {
        s1 = (lane < 8) ? r1[lane] : 0.f;
        s2 = (lane < 8) ? r2[lane] : 0.f;
#pragma unroll
        for (int off = 4; off; off >>= 1) {
            s1 += __shfl_xor_sync(0xffffffffu, s1, off);
            s2 += __shfl_xor_sync(0xffffffffu, s2, off);
        }
        if (lane == 0) { r1[0] = s1; r2[0] = s2; }
    }
    __syncthreads();
    s1 = r1[0]; s2 = r2[0];
}

__global__ __launch_bounds__(256) void ln_kernel(
    const float* __restrict__ X, const float* __restrict__ g,
    const float* __restrict__ bta, float* __restrict__ out)
{
    size_t row = blockIdx.x;
    const float* x = X + row * EE;
    int c = threadIdx.x * 4;
    float4 v = *(const float4*)(x + c);
    float s1 = v.x + v.y + v.z + v.w;
    float s2 = v.x * v.x + v.y * v.y + v.z * v.z + v.w * v.w;
    block_reduce2(s1, s2);
    float mu = s1 * (1.f / EE);
    float var = s2 * (1.f / EE) - mu * mu;
    float rs = rsqrtf(var + 1e-5f);
    float4 gg = *(const float4*)(g + c);
    float4 bb = *(const float4*)(bta + c);
    float4 o;
    o.x = (v.x - mu) * rs * gg.x + bb.x;
    o.y = (v.y - mu) * rs * gg.y + bb.y;
    o.z = (v.z - mu) * rs * gg.z + bb.z;
    o.w = (v.w - mu) * rs * gg.w + bb.w;
    *(float4*)(out + row * EE + c) = o;
}

__global__ __launch_bounds__(256) void newmem_kernel(
    const float* __restrict__ gmemM,
    const float* __restrict__ gupd,
    const float* __restrict__ upd,
    const float* __restrict__ memv,
    const float* __restrict__ wg, const float* __restrict__ wb,
    float* __restrict__ out)
{
    int row = blockIdx.x;
    int b = row >> 9, m = row & 511;
    int c = threadIdx.x * 4;
    float4 gm = *(const float4*)(gmemM + (size_t)m * EE + c);
    float4 gu = *(const float4*)(gupd + (size_t)b * EE + c);
    float4 uv = *(const float4*)(upd + (size_t)b * EE + c);
    float4 mv = *(const float4*)(memv + (size_t)m * EE + c);
    float ge[4] = {gm.x + gu.x, gm.y + gu.y, gm.z + gu.z, gm.w + gu.w};
    float u[4] = {uv.x, uv.y, uv.z, uv.w};
    float mmv[4] = {mv.x, mv.y, mv.z, mv.w};
    float x[4];
    float s1 = 0.f, s2 = 0.f;
#pragma unroll
    for (int i = 0; i < 4; i++) {
        float gt = 1.f / (1.f + __expf(-ge[i]));
        x[i] = gt * u[i] + (1.f - gt) * mmv[i];
        s1 += x[i]; s2 += x[i] * x[i];
    }
    block_reduce2(s1, s2);
    float mu = s1 * (1.f / EE);
    float var = s2 * (1.f / EE) - mu * mu;
    float rs = rsqrtf(var + 1e-5f);
    float4 gg = *(const float4*)(wg + c);
    float4 bb = *(const float4*)(wb + c);
    float4 o;
    o.x = (x[0] - mu) * rs * gg.x + bb.x;
    o.y = (x[1] - mu) * rs * gg.y + bb.y;
    o.z = (x[2] - mu) * rs * gg.z + bb.z;
    o.w = (x[3] - mu) * rs * gg.w + bb.w;
    *(float4*)(out + (size_t)row * EE + c) = o;
}

__global__ __launch_bounds__(256) void mean_kernel(
    const float* __restrict__ q, float* __restrict__ wq)
{
    __shared__ float red[8][33];
    int b = blockIdx.y;
    int e0 = blockIdx.x * 32;
    int el = threadIdx.x & 31, strip = threadIdx.x >> 5;
    const float* p = q + ((size_t)b * SS + strip * 256) * EE + e0 + el;
    float s = 0.f;
#pragma unroll 4
    for (int i = 0; i < 256; i++) s += p[(size_t)i * EE];
    red[strip][el] = s;
    __syncthreads();
    if (strip == 0) {
        float t = 0.f;
#pragma unroll
        for (int k = 0; k < 8; k++) t += red[k][el];
        wq[(size_t)b * EE + e0 + el] = t * (1.f / SS);
    }
}

__global__ __launch_bounds__(256) void gemv8(
    const float* __restrict__ A,
    const float* __restrict__ B, int ldb,
    const float* __restrict__ bias,
    float* __restrict__ C, int N, int K)
{
    int w = threadIdx.x >> 5, lane = threadIdx.x & 31;
    int n = blockIdx.x * 8 + w;
    if (n >= N) return;
    const float* brow = B + (size_t)n * ldb;
    for (int b = 0; b < BB; b++) {
        const float* arow = A + (size_t)b * K;
        float s = 0.f;
        for (int i = lane; i < K; i += 32) s += arow[i] * brow[i];
#pragma unroll
        for (int off = 16; off; off >>= 1) s += __shfl_xor_sync(0xffffffffu, s, off);
        if (lane == 0) C[(size_t)b * N + n] = s + (bias ? bias[n] : 0.f);
    }
}

// ---------------------------------------------------------------------------
extern "C" void kernel_launch(void* const* d_in, const int* in_sizes, int n_in,
                              void* d_out, int out_size)
{
    (void)in_sizes; (void)n_in; (void)out_size;
    const float* query   = (const float*)d_in[0];
    const float* memory  = (const float*)d_in[1];
    const float* r_in_w  = (const float*)d_in[2];
    const float* r_in_b  = (const float*)d_in[3];
    const float* r_out_w = (const float*)d_in[4];
    const float* r_out_b = (const float*)d_in[5];
    const float* w_in_w  = (const float*)d_in[6];
    const float* w_in_b  = (const float*)d_in[7];
    const float* w_out_w = (const float*)d_in[8];
    const float* w_out_b = (const float*)d_in[9];
    const float* rn_g    = (const float*)d_in[10];
    const float* rn_b    = (const float*)d_in[11];
    const float* wn_g    = (const float*)d_in[12];
    const float* wn_b    = (const float*)d_in[13];
    const float* gate_w  = (const float*)d_in[14];
    const float* gate_b  = (const float*)d_in[15];
    float* out = (float*)d_out;

    float *KV, *y, *wq, *vw, *upd, *gmem, *gupd;
    cudaGetSymbolAddress((void**)&KV,   g_KV);
    cudaGetSymbolAddress((void**)&y,    g_y);
    cudaGetSymbolAddress((void**)&wq,   g_wq);
    cudaGetSymbolAddress((void**)&vw,   g_vw);
    cudaGetSymbolAddress((void**)&upd,  g_upd);
    cudaGetSymbolAddress((void**)&gmem, g_gmem);
    cudaGetSymbolAddress((void**)&gupd, g_gupd);

    __nv_bfloat16 *qh, *ql, *qph, *qpl, *ahp, *alp, *mh, *ml, *kh, *kl, *vth, *vtl;
    __nv_bfloat16 *riwh, *riwl, *rowh, *rowl, *gwh, *gwl;
    cudaGetSymbolAddress((void**)&qh,   g_qh);
    cudaGetSymbolAddress((void**)&ql,   g_ql);
    cudaGetSymbolAddress((void**)&qph,  g_qph);
    cudaGetSymbolAddress((void**)&qpl,  g_qpl);
    cudaGetSymbolAddress((void**)&ahp,  g_ah);
    cudaGetSymbolAddress((void**)&alp,  g_al);
    cudaGetSymbolAddress((void**)&mh,   g_mh);
    cudaGetSymbolAddress((void**)&ml,   g_ml);
    cudaGetSymbolAddress((void**)&kh,   g_kh);
    cudaGetSymbolAddress((void**)&kl,   g_kl);
    cudaGetSymbolAddress((void**)&vth,  g_vth);
    cudaGetSymbolAddress((void**)&vtl,  g_vtl);
    cudaGetSymbolAddress((void**)&riwh, g_riwh);
    cudaGetSymbolAddress((void**)&riwl, g_riwl);
    cudaGetSymbolAddress((void**)&rowh, g_rowh);
    cudaGetSymbolAddress((void**)&rowl, g_rowl);
    cudaGetSymbolAddress((void**)&gwh,  g_gwh);
    cudaGetSymbolAddress((void**)&gwl,  g_gwl);

    cudaFuncSetAttribute(gemm_mma, cudaFuncAttributeMaxDynamicSharedMemorySize, GSMEM);
    cudaFuncSetAttribute(attn_mma, cudaFuncAttributeMaxDynamicSharedMemorySize, AT_SMEM);

    // --- split conversions (inputs + weights) ---
    cvt_split<<<3 * EE * EE / 1024, 256>>>(r_in_w, riwh, riwl, 3 * EE * EE);
    cvt_split<<<EE * EE / 1024, 256>>>(r_out_w, rowh, rowl, EE * EE);
    cvt_split<<<2 * EE * EE / 1024, 256>>>(gate_w, gwh, gwl, 2 * EE * EE);
    cvt_split<<<MM * EE / 1024, 256>>>(memory, mh, ml, MM * EE);
    cvt_split<<<BB * SS * EE / 1024, 256>>>(query, qh, ql, BB * SS * EE);

    // --- r-branch ---
    gemm_mma<<<dim3(2 * EE / 128, MM / 128), 256, GSMEM>>>(
        mh, ml, EE, riwh + (size_t)EE * EE, riwl + (size_t)EE * EE, EE,
        r_in_b + EE, nullptr, KV, nullptr, nullptr, 2 * EE, 1.f);
    split_k<<<MM, 256>>>(KV, kh, kl);
    transpose_v<<<dim3(EE / 32, MM / 32), 256>>>(KV, vth, vtl);
    gemm_mma<<<dim3(EE / 128, BB * SS / 128), 256, GSMEM>>>(
        qh, ql, EE, riwh, riwl, EE,
        r_in_b, nullptr, nullptr, qph, qpl, EE, 0.125f);
    attn_mma<<<dim3(SS / 64, HH, BB), 128, AT_SMEM>>>(
        qph, qpl, kh, kl, vth, vtl, ahp, alp);
    gemm_mma<<<dim3(EE / 128, BB * SS / 128), 256, GSMEM>>>(
        ahp, alp, EE, rowh, rowl, EE,
        r_out_b, query, y, nullptr, nullptr, EE, 1.f);
    ln_kernel<<<BB * SS, 256>>>(y, rn_g, rn_b, out);

    // --- w-branch (collapsed) ---
    mean_kernel<<<dim3(EE / 32, BB), 256>>>(query, wq);
    gemv8<<<EE / 8, 256>>>(wq, w_in_w + (size_t)2 * EE * EE, EE, w_in_b + 2 * EE, vw, EE, EE);
    gemv8<<<EE / 8, 256>>>(vw, w_out_w, EE, w_out_b, upd, EE, EE);

    // --- gate (decomposed) ---
    gemm_mma<<<dim3(EE / 128, MM / 128), 256, GSMEM>>>(
        mh, ml, EE, gwh, gwl, 2 * EE,
        gate_b, nullptr, gmem, nullptr, nullptr, EE, 1.f);
    gemv8<<<EE / 8, 256>>>(upd, gate_w + EE, 2 * EE, nullptr, gupd, EE, EE);

    newmem_kernel<<<BB * MM, 256>>>(gmem, gupd, upd, memory, wn_g, wn_b,
                                    out + (size_t)BB * SS * EE);
}

// round 11
// speedup vs baseline: 3.2199x; 1.0032x over previous
#include <cuda_runtime.h>
#include <cuda_bf16.h>
#include <math.h>
#include <stdint.h>

// ---------------------------------------------------------------------------
// Problem constants
// ---------------------------------------------------------------------------
#define BB 8
#define SS 2048
#define MM 512
#define EE 1024
#define HH 16
#define DD 64

// ---------------------------------------------------------------------------
// Scratch (device globals; no allocation allowed)
// ---------------------------------------------------------------------------
__device__ float g_KV[MM * 2 * EE];
__device__ float g_y[BB * SS * EE];
__device__ float g_wq[BB * EE];
__device__ float g_vw[BB * EE];
__device__ float g_upd[BB * EE];
__device__ float g_gmem[MM * EE];
__device__ float g_gupd[BB * EE];

// bf16 hi/lo split buffers
__device__ __nv_bfloat16 g_qh[BB * SS * EE];
__device__ __nv_bfloat16 g_ql[BB * SS * EE];
__device__ __nv_bfloat16 g_qph[BB * SS * EE];
__device__ __nv_bfloat16 g_qpl[BB * SS * EE];
__device__ __nv_bfloat16 g_ah[BB * SS * EE];
__device__ __nv_bfloat16 g_al[BB * SS * EE];
__device__ __nv_bfloat16 g_mh[MM * EE];
__device__ __nv_bfloat16 g_ml[MM * EE];
__device__ __nv_bfloat16 g_kh[MM * EE];
__device__ __nv_bfloat16 g_kl[MM * EE];
__device__ __nv_bfloat16 g_vth[EE * MM];
__device__ __nv_bfloat16 g_vtl[EE * MM];
__device__ __nv_bfloat16 g_riwh[3 * EE * EE];
__device__ __nv_bfloat16 g_riwl[3 * EE * EE];
__device__ __nv_bfloat16 g_rowh[EE * EE];
__device__ __nv_bfloat16 g_rowl[EE * EE];
__device__ __nv_bfloat16 g_gwh[EE * 2 * EE];
__device__ __nv_bfloat16 g_gwl[EE * 2 * EE];

// ---------------------------------------------------------------------------
// PTX helpers
// ---------------------------------------------------------------------------
__device__ __forceinline__ uint32_t smem_u32(const void* p) {
    uint32_t a;
    asm("{ .reg .u64 t; cvta.to.shared.u64 t, %1; cvt.u32.u64 %0, t; }" : "=r"(a) : "l"(p));
    return a;
}

#define CP_COMMIT() asm volatile("cp.async.commit_group;" ::: "memory")
#define CP_WAIT(n)  asm volatile("cp.async.wait_group %0;" :: "n"(n) : "memory")

__device__ __forceinline__ void cp16(uint32_t saddr, const void* g) {
    asm volatile("cp.async.cg.shared.global [%0], [%1], 16;" :: "r"(saddr), "l"(g) : "memory");
}

__device__ __forceinline__ void ldsm_x4(uint32_t& r0, uint32_t& r1, uint32_t& r2,
                                        uint32_t& r3, uint32_t addr) {
    asm volatile("ldmatrix.sync.aligned.m8n8.x4.shared.b16 {%0,%1,%2,%3}, [%4];"
                 : "=r"(r0), "=r"(r1), "=r"(r2), "=r"(r3) : "r"(addr));
}

__device__ __forceinline__ void mma_16816(float* d, const uint32_t* a,
                                          uint32_t b0, uint32_t b1) {
    asm volatile(
        "mma.sync.aligned.m16n8k16.row.col.f32.bf16.bf16.f32 "
        "{%0,%1,%2,%3}, {%4,%5,%6,%7}, {%8,%9}, {%0,%1,%2,%3};"
        : "+f"(d[0]), "+f"(d[1]), "+f"(d[2]), "+f"(d[3])
        : "r"(a[0]), "r"(a[1]), "r"(a[2]), "r"(a[3]), "r"(b0), "r"(b1));
}

__device__ __forceinline__ uint32_t pack_bf2(float a, float b) {
    __nv_bfloat162 t = __floats2bfloat162_rn(a, b);
    return *reinterpret_cast<uint32_t*>(&t);
}
__device__ __forceinline__ float bf_res(float x) {
    return x - __bfloat162float(__float2bfloat16_rn(x));
}

// ---------------------------------------------------------------------------
// hi/lo bf16 split conversion
// ---------------------------------------------------------------------------
__global__ __launch_bounds__(256) void cvt_split(
    const float* __restrict__ x, __nv_bfloat16* __restrict__ hi,
    __nv_bfloat16* __restrict__ lo, int n)
{
    int i = (blockIdx.x * 256 + threadIdx.x) * 4;
    if (i >= n) return;
    float4 v = *(const float4*)(x + i);
    __nv_bfloat16 h0 = __float2bfloat16_rn(v.x);
    __nv_bfloat16 h1 = __float2bfloat16_rn(v.y);
    __nv_bfloat16 h2 = __float2bfloat16_rn(v.z);
    __nv_bfloat16 h3 = __float2bfloat16_rn(v.w);
    *(__nv_bfloat162*)(hi + i)     = __halves2bfloat162(h0, h1);
    *(__nv_bfloat162*)(hi + i + 2) = __halves2bfloat162(h2, h3);
    *(__nv_bfloat162*)(lo + i)     = __halves2bfloat162(
        __float2bfloat16_rn(v.x - __bfloat162float(h0)),
        __float2bfloat16_rn(v.y - __bfloat162float(h1)));
    *(__nv_bfloat162*)(lo + i + 2) = __halves2bfloat162(
        __float2bfloat16_rn(v.z - __bfloat162float(h2)),
        __float2bfloat16_rn(v.w - __bfloat162float(h3)));
}

// ---------------------------------------------------------------------------
// KV prep
// ---------------------------------------------------------------------------
__global__ __launch_bounds__(256) void split_k(
    const float* __restrict__ KV, __nv_bfloat16* __restrict__ kh,
    __nv_bfloat16* __restrict__ kl)
{
    int j = blockIdx.x;
    int c = threadIdx.x * 4;
    float4 v = *(const float4*)(KV + (size_t)j * (2 * EE) + c);
    __nv_bfloat16 h0 = __float2bfloat16_rn(v.x);
    __nv_bfloat16 h1 = __float2bfloat16_rn(v.y);
    __nv_bfloat16 h2 = __float2bfloat16_rn(v.z);
    __nv_bfloat16 h3 = __float2bfloat16_rn(v.w);
    size_t o = (size_t)j * EE + c;
    *(__nv_bfloat162*)(kh + o)     = __halves2bfloat162(h0, h1);
    *(__nv_bfloat162*)(kh + o + 2) = __halves2bfloat162(h2, h3);
    *(__nv_bfloat162*)(kl + o)     = __halves2bfloat162(
        __float2bfloat16_rn(v.x - __bfloat162float(h0)),
        __float2bfloat16_rn(v.y - __bfloat162float(h1)));
    *(__nv_bfloat162*)(kl + o + 2) = __halves2bfloat162(
        __float2bfloat16_rn(v.z - __bfloat162float(h2)),
        __float2bfloat16_rn(v.w - __bfloat162float(h3)));
}

__global__ __launch_bounds__(256) void transpose_v(
    const float* __restrict__ KV, __nv_bfloat16* __restrict__ vth,
    __nv_bfloat16* __restrict__ vtl)
{
    __shared__ float t[32][33];
    int e0 = blockIdx.x * 32, j0 = blockIdx.y * 32;
    int tx = threadIdx.x & 31, ty = threadIdx.x >> 5;
#pragma unroll
    for (int k2 = 0; k2 < 4; k2++)
        t[ty + k2 * 8][tx] = KV[(size_t)(j0 + ty + k2 * 8) * (2 * EE) + EE + e0 + tx];
    __syncthreads();
#pragma unroll
    for (int k2 = 0; k2 < 4; k2++) {
        float v = t[tx][ty + k2 * 8];
        __nv_bfloat16 hv = __float2bfloat16_rn(v);
        size_t o = (size_t)(e0 + ty + k2 * 8) * MM + j0 + tx;
        vth[o] = hv;
        vtl[o] = __float2bfloat16_rn(v - __bfloat162float(hv));
    }
}

// ---------------------------------------------------------------------------
// HMMA split-bf16 GEMM (NT), FUSED 3-pass (unchanged from R8)
// ---------------------------------------------------------------------------
#define GSTAGE 32768
#define GSMEM  (3 * GSTAGE)

__global__ __launch_bounds__(256, 2) void gemm_mma(
    const __nv_bfloat16* __restrict__ Ah, const __nv_bfloat16* __restrict__ Al, int lda,
    const __nv_bfloat16* __restrict__ Bh, const __nv_bfloat16* __restrict__ Bl, int ldb,
    const float* __restrict__ bias, const float* __restrict__ res,
    float* __restrict__ C,
    __nv_bfloat16* __restrict__ Chi, __nv_bfloat16* __restrict__ Clo,
    int N, float scale)
{
    extern __shared__ char smem[];
    const uint32_t sbase = smem_u32(smem);
    const int tid = threadIdx.x;
    const int wid = tid >> 5, lane = tid & 31;
    const int wm = wid >> 2, wn = wid & 3;
    const int mbase = blockIdx.y * 128;
    const int nbase = blockIdx.x * 128;

    float acc[4][4][4];
#pragma unroll
    for (int i = 0; i < 4; i++)
#pragma unroll
        for (int j = 0; j < 4; j++)
#pragma unroll
            for (int k = 0; k < 4; k++) acc[i][j][k] = 0.f;

    auto load_stage = [&](int kt, int buf) {
        uint32_t st = sbase + (uint32_t)buf * GSTAGE;
#pragma unroll
        for (int j = 0; j < 2; j++) {
            int u = tid + j * 256;
            int r = u >> 2, c = u & 3;
            int cs = c ^ ((r >> 1) & 3);
            uint32_t dst = st + r * 64 + cs * 16;
            size_t aoff = (size_t)(mbase + r) * lda + kt * 32 + c * 8;
            size_t boff = (size_t)(nbase + r) * ldb + kt * 32 + c * 8;
            cp16(dst, Ah + aoff);
            cp16(dst + 8192, Al + aoff);
            cp16(dst + 16384, Bh + boff);
            cp16(dst + 24576, Bl + boff);
        }
    };

    const int NCH = 32;
    load_stage(0, 0); CP_COMMIT();
    load_stage(1, 1); CP_COMMIT();

    for (int s = 0; s < NCH; ++s) {
        int pf = s + 2;
        if (pf < NCH) {
            load_stage(pf, pf % 3);
            CP_COMMIT();
            CP_WAIT(2);
        } else {
            CP_WAIT(0);
        }
        __syncthreads();

        uint32_t st = sbase + (uint32_t)(s % 3) * GSTAGE;

#pragma unroll
        for (int kk = 0; kk < 2; kk++) {
            uint32_t ah_f[4][4], al_f[4][4], b_f[2][4];
#pragma unroll
            for (int mi = 0; mi < 4; mi++) {
                int r = wm * 64 + mi * 16 + (lane & 15);
                int c = kk * 2 + (lane >> 4);
                int cs = c ^ ((r >> 1) & 3);
                ldsm_x4(ah_f[mi][0], ah_f[mi][1], ah_f[mi][2], ah_f[mi][3],
                        st + r * 64 + cs * 16);
            }
#pragma unroll
            for (int nb = 0; nb < 2; nb++) {
                int r = wn * 32 + nb * 16 + ((lane >> 4) << 3) + (lane & 7);
                int c = kk * 2 + ((lane >> 3) & 1);
                int cs = c ^ ((r >> 1) & 3);
                ldsm_x4(b_f[nb][0], b_f[nb][1], b_f[nb][2], b_f[nb][3],
                        st + 16384 + r * 64 + cs * 16);
            }
#pragma unroll
            for (int mi = 0; mi < 4; mi++)
#pragma unroll
                for (int ni = 0; ni < 4; ni++) {
                    int nb = ni >> 1, hh = ni & 1;
                    mma_16816(acc[mi][ni], ah_f[mi], b_f[nb][hh * 2], b_f[nb][hh * 2 + 1]);
                }
#pragma unroll
            for (int mi = 0; mi < 4; mi++) {
                int r = wm * 64 + mi * 16 + (lane & 15);
                int c = kk * 2 + (lane >> 4);
                int cs = c ^ ((r >> 1) & 3);
                ldsm_x4(al_f[mi][0], al_f[mi][1], al_f[mi][2], al_f[mi][3],
                        st + 8192 + r * 64 + cs * 16);
            }
#pragma unroll
            for (int mi = 0; mi < 4; mi++)
#pragma unroll
                for (int ni = 0; ni < 4; ni++) {
                    int nb = ni >> 1, hh = ni & 1;
                    mma_16816(acc[mi][ni], al_f[mi], b_f[nb][hh * 2], b_f[nb][hh * 2 + 1]);
                }
#pragma unroll
            for (int nb = 0; nb < 2; nb++) {
                int r = wn * 32 + nb * 16 + ((lane >> 4) << 3) + (lane & 7);
                int c = kk * 2 + ((lane >> 3) & 1);
                int cs = c ^ ((r >> 1) & 3);
                ldsm_x4(b_f[nb][0], b_f[nb][1], b_f[nb][2], b_f[nb][3],
                        st + 24576 + r * 64 + cs * 16);
            }
#pragma unroll
            for (int mi = 0; mi < 4; mi++)
#pragma unroll
                for (int ni = 0; ni < 4; ni++) {
                    int nb = ni >> 1, hh = ni & 1;
                    mma_16816(acc[mi][ni], ah_f[mi], b_f[nb][hh * 2], b_f[nb][hh * 2 + 1]);
                }
        }
        __syncthreads();
    }

    const int r_lo = lane >> 2;
    const int c_off = (lane & 3) * 2;
#pragma unroll
    for (int mi = 0; mi < 4; mi++) {
        size_t row = (size_t)mbase + wm * 64 + mi * 16 + r_lo;
#pragma unroll
        for (int ni = 0; ni < 4; ni++) {
            int col = nbase + wn * 32 + ni * 8 + c_off;
            const float* a4 = acc[mi][ni];
            float2 bv = *(const float2*)(bias + col);
            float2 v0, v1;
            v0.x = scale * (a4[0] + bv.x); v0.y = scale * (a4[1] + bv.y);
            v1.x = scale * (a4[2] + bv.x); v1.y = scale * (a4[3] + bv.y);
            if (Chi) {
                *(uint32_t*)(Chi + row * N + col)       = pack_bf2(v0.x, v0.y);
                *(uint32_t*)(Chi + (row + 8) * N + col) = pack_bf2(v1.x, v1.y);
                *(uint32_t*)(Clo + row * N + col)       = pack_bf2(bf_res(v0.x), bf_res(v0.y));
                *(uint32_t*)(Clo + (row + 8) * N + col) = pack_bf2(bf_res(v1.x), bf_res(v1.y));
            } else {
                if (res) {
                    float2 r0 = *(const float2*)(res + row * N + col);
                    float2 r1 = *(const float2*)(res + (row + 8) * N + col);
                    v0.x += r0.x; v0.y += r0.y; v1.x += r1.x; v1.y += r1.y;
                }
                *(float2*)(C + row * N + col) = v0;
                *(float2*)(C + (row + 8) * N + col) = v1;
            }
        }
    }
}

// ---------------------------------------------------------------------------
// HMMA flash attention: q-tile 128, 256 threads (8 warps x 16 rows), 2 CTAs/SM.
// K/V chunks of 64 keys, double-buffered. Q fragments re-loaded per kk to
// stay under the 128-reg cap.
// ---------------------------------------------------------------------------
#define AT_STAGE 32768
#define AT_SMEM  (32768 + 2 * AT_STAGE)

__global__ __launch_bounds__(256, 2) void attn_mma(
    const __nv_bfloat16* __restrict__ qh, const __nv_bfloat16* __restrict__ ql,
    const __nv_bfloat16* __restrict__ kh, const __nv_bfloat16* __restrict__ kl,
    const __nv_bfloat16* __restrict__ vth, const __nv_bfloat16* __restrict__ vtl,
    __nv_bfloat16* __restrict__ ah, __nv_bfloat16* __restrict__ al)
{
    extern __shared__ char smem[];
    const uint32_t sb = smem_u32(smem);
    const int b = blockIdx.z, h = blockIdx.y;
    const int s0 = blockIdx.x * 128;
    const int tid = threadIdx.x, w = tid >> 5, lane = tid & 31;

    const uint32_t sQh = sb, sQl = sb + 16384;
    const uint32_t sStage = sb + 32768;

    auto loadKV = [&](int c, int buf) {
        uint32_t st = sStage + (uint32_t)buf * AT_STAGE;
        int j0 = c * 64;
#pragma unroll
        for (int it = 0; it < 2; it++) {
            int u = tid + it * 256;
            int r = u >> 3, cc = u & 7, cs = cc ^ (r & 7);
            size_t koff = (size_t)(j0 + r) * EE + h * DD + cc * 8;
            cp16(st + r * 128 + cs * 16, kh + koff);
            cp16(st + 8192 + r * 128 + cs * 16, kl + koff);
            size_t voff = (size_t)(h * DD + r) * MM + j0 + cc * 8;
            cp16(st + 16384 + r * 128 + cs * 16, vth + voff);
            cp16(st + 24576 + r * 128 + cs * 16, vtl + voff);
        }
    };

    {
#pragma unroll
        for (int it = 0; it < 4; it++) {
            int u = tid + it * 256;
            int r = u >> 3, cc = u & 7, cs = cc ^ (r & 7);
            size_t off = ((size_t)(b * SS + s0 + r)) * EE + h * DD + cc * 8;
            cp16(sQh + r * 128 + cs * 16, qh + off);
            cp16(sQl + r * 128 + cs * 16, ql + off);
        }
        loadKV(0, 0);
        CP_COMMIT();
    }

    float m0 = -1e30f, m1 = -1e30f, l0 = 0.f, l1 = 0.f;
    float out[4][2][4];
#pragma unroll
    for (int g = 0; g < 4; g++)
#pragma unroll
        for (int s2 = 0; s2 < 2; s2++)
#pragma unroll
            for (int k = 0; k < 4; k++) out[g][s2][k] = 0.f;

    for (int c = 0; c < 8; c++) {
        if (c < 7) {
            loadKV(c + 1, (c + 1) & 1);
            CP_COMMIT();
            CP_WAIT(1);
        } else {
            CP_WAIT(0);
        }
        __syncthreads();

        uint32_t stK = sStage + (uint32_t)(c & 1) * AT_STAGE;
        uint32_t stKl = stK + 8192, stVh = stK + 16384, stVl = stK + 24576;

        float sc[4][2][4];
#pragma unroll
        for (int g = 0; g < 4; g++)
#pragma unroll
            for (int s2 = 0; s2 < 2; s2++)
#pragma unroll
                for (int k = 0; k < 4; k++) sc[g][s2][k] = 0.f;

        const int rb_ = ((lane >> 4) << 3) + (lane & 7);
#pragma unroll
        for (int kk = 0; kk < 4; kk++) {
            // Q fragments for this kk (hi + lo)
            uint32_t qfh[4], qfl[4];
            {
                int rq = w * 16 + (lane & 15);
                int cq = kk * 2 + (lane >> 4);
                int csq = cq ^ (rq & 7);
                ldsm_x4(qfh[0], qfh[1], qfh[2], qfh[3], sQh + rq * 128 + csq * 16);
                ldsm_x4(qfl[0], qfl[1], qfl[2], qfl[3], sQl + rq * 128 + csq * 16);
            }
            const int ccb = kk * 2 + ((lane >> 3) & 1);
            uint32_t bk[4][4];
#pragma unroll
            for (int g = 0; g < 4; g++) {
                int r = g * 16 + rb_;
                int cs = ccb ^ (r & 7);
                ldsm_x4(bk[g][0], bk[g][1], bk[g][2], bk[g][3], stK + r * 128 + cs * 16);
            }
#pragma unroll
            for (int g = 0; g < 4; g++)
#pragma unroll
                for (int s2 = 0; s2 < 2; s2++) {
                    mma_16816(sc[g][s2], qfh, bk[g][s2 * 2], bk[g][s2 * 2 + 1]);
                    mma_16816(sc[g][s2], qfl, bk[g][s2 * 2], bk[g][s2 * 2 + 1]);
                }
#pragma unroll
            for (int g = 0; g < 4; g++) {
                int r = g * 16 + rb_;
                int cs = ccb ^ (r & 7);
                ldsm_x4(bk[g][0], bk[g][1], bk[g][2], bk[g][3], stKl + r * 128 + cs * 16);
            }
#pragma unroll
            for (int g = 0; g < 4; g++)
#pragma unroll
                for (int s2 = 0; s2 < 2; s2++)
                    mma_16816(sc[g][s2], qfh, bk[g][s2 * 2], bk[g][s2 * 2 + 1]);
        }

        float rmax0 = -1e30f, rmax1 = -1e30f;
#pragma unroll
        for (int g = 0; g < 4; g++)
#pragma unroll
            for (int s2 = 0; s2 < 2; s2++) {
                rmax0 = fmaxf(rmax0, fmaxf(sc[g][s2][0], sc[g][s2][1]));
                rmax1 = fmaxf(rmax1, fmaxf(sc[g][s2][2], sc[g][s2][3]));
            }
        rmax0 = fmaxf(rmax0, __shfl_xor_sync(0xffffffffu, rmax0, 1));
        rmax0 = fmaxf(rmax0, __shfl_xor_sync(0xffffffffu, rmax0, 2));
        rmax1 = fmaxf(rmax1, __shfl_xor_sync(0xffffffffu, rmax1, 1));
        rmax1 = fmaxf(rmax1, __shfl_xor_sync(0xffffffffu, rmax1, 2));
        float nm0 = fmaxf(m0, rmax0), nm1 = fmaxf(m1, rmax1);
        float f0 = __expf(m0 - nm0), f1 = __expf(m1 - nm1);
        m0 = nm0; m1 = nm1;
        float ps0 = 0.f, ps1 = 0.f;
#pragma unroll
        for (int g = 0; g < 4; g++)
#pragma unroll
            for (int s2 = 0; s2 < 2; s2++) {
                sc[g][s2][0] = __expf(sc[g][s2][0] - m0);
                sc[g][s2][1] = __expf(sc[g][s2][1] - m0);
                sc[g][s2][2] = __expf(sc[g][s2][2] - m1);
                sc[g][s2][3] = __expf(sc[g][s2][3] - m1);
                ps0 += sc[g][s2][0] + sc[g][s2][1];
                ps1 += sc[g][s2][2] + sc[g][s2][3];
            }
        ps0 += __shfl_xor_sync(0xffffffffu, ps0, 1);
        ps0 += __shfl_xor_sync(0xffffffffu, ps0, 2);
        ps1 += __shfl_xor_sync(0xffffffffu, ps1, 1);
        ps1 += __shfl_xor_sync(0xffffffffu, ps1, 2);
        l0 = l0 * f0 + ps0;
        l1 = l1 * f1 + ps1;
#pragma unroll
        for (int g = 0; g < 4; g++)
#pragma unroll
            for (int s2 = 0; s2 < 2; s2++) {
                out[g][s2][0] *= f0; out[g][s2][1] *= f0;
                out[g][s2][2] *= f1; out[g][s2][3] *= f1;
            }

#pragma unroll
        for (int kk = 0; kk < 4; kk++) {
            uint32_t pah[4], pal[4];
            pah[0] = pack_bf2(sc[kk][0][0], sc[kk][0][1]);
            pah[1] = pack_bf2(sc[kk][0][2], sc[kk][0][3]);
            pah[2] = pack_bf2(sc[kk][1][0], sc[kk][1][1]);
            pah[3] = pack_bf2(sc[kk][1][2], sc[kk][1][3]);
            pal[0] = pack_bf2(bf_res(sc[kk][0][0]), bf_res(sc[kk][0][1]));
            pal[1] = pack_bf2(bf_res(sc[kk][0][2]), bf_res(sc[kk][0][3]));
            pal[2] = pack_bf2(bf_res(sc[kk][1][0]), bf_res(sc[kk][1][1]));
            pal[3] = pack_bf2(bf_res(sc[kk][1][2]), bf_res(sc[kk][1][3]));

            const int ccb = kk * 2 + ((lane >> 3) & 1);
            uint32_t bv[4][4];
#pragma unroll
            for (int g = 0; g < 4; g++) {
                int r = g * 16 + rb_;
                int cs = ccb ^ (r & 7);
                ldsm_x4(bv[g][0], bv[g][1], bv[g][2], bv[g][3], stVh + r * 128 + cs * 16);
            }
#pragma unroll
            for (int g = 0; g < 4; g++)
#pragma unroll
                for (int s2 = 0; s2 < 2; s2++) {
                    mma_16816(out[g][s2], pah, bv[g][s2 * 2], bv[g][s2 * 2 + 1]);
                    mma_16816(out[g][s2], pal, bv[g][s2 * 2], bv[g][s2 * 2 + 1]);
                }
#pragma unroll
            for (int g = 0; g < 4; g++) {
                int r = g * 16 + rb_;
                int cs = ccb ^ (r & 7);
                ldsm_x4(bv[g][0], bv[g][1], bv[g][2], bv[g][3], stVl + r * 128 + cs * 16);
            }
#pragma unroll
            for (int g = 0; g < 4; g++)
#pragma unroll
                for (int s2 = 0; s2 < 2; s2++)
                    mma_16816(out[g][s2], pah, bv[g][s2 * 2], bv[g][s2 * 2 + 1]);
        }
        __syncthreads();
    }

    float inv0 = 1.f / l0, inv1 = 1.f / l1;
    size_t row0 = (size_t)(b * SS) + s0 + w * 16 + (lane >> 2);
#pragma unroll
    for (int g = 0; g < 4; g++)
#pragma unroll
        for (int s2 = 0; s2 < 2; s2++) {
            int col = h * DD + g * 16 + s2 * 8 + (lane & 3) * 2;
            float v0 = out[g][s2][0] * inv0, v1 = out[g][s2][1] * inv0;
            float v2 = out[g][s2][2] * inv1, v3 = out[g][s2][3] * inv1;
            *(uint32_t*)(ah + row0 * EE + col)       = pack_bf2(v0, v1);
            *(uint32_t*)(ah + (row0 + 8) * EE + col) = pack_bf2(v2, v3);
            *(uint32_t*)(al + row0 * EE + col)       = pack_bf2(bf_res(v0), bf_res(v1));
            *(uint32_t*)(al + (row0 + 8) * EE + col) = pack_bf2(bf_res(v2), bf_res(v3));
        }
}

// ---------------------------------------------------------------------------
// Pointwise / reduction kernels
// ---------------------------------------------------------------------------
__device__ __forceinline__ void block_reduce2(float& s1, float& s2) {
    __shared__ float r1[8], r2[8];
    int lane = threadIdx.x & 31, w = threadIdx.x >> 5;
#pragma unroll
    for (int off = 16; off; off >>= 1) {
        s1 += __shfl_xor_sync(0xffffffffu, s1, off);
        s2 += __shfl_xor_sync(0xffffffffu, s2, off);
    }
    if (lane == 0) { r1[w] = s1; r2[w] = s2; }
    __syncthreads();
    if (w == 0) {
        s1 = (lane < 8) ? r1[lane] : 0.f;
        s2 = (lane < 8) ? r2[lane] : 0.f;
#pragma unroll
        for (int off = 4; off; off >>= 1) {
            s1 += __shfl_xor_sync(0xffffffffu, s1, off);
            s2 += __shfl_xor_sync(0xffffffffu, s2, off);
        }
        if (lane == 0) { r1[0] = s1; r2[0] = s2; }
    }
    __syncthreads();
    s1 = r1[0]; s2 = r2[0];
}

__global__ __launch_bounds__(256) void ln_kernel(
    const float* __restrict__ X, const float* __restrict__ g,
    const float* __restrict__ bta, float* __restrict__ out)
{
    size_t row = blockIdx.x;
    const float* x = X + row * EE;
    int c = threadIdx.x * 4;
    float4 v = *(const float4*)(x + c);
    float s1 = v.x + v.y + v.z + v.w;
    float s2 = v.x * v.x + v.y * v.y + v.z * v.z + v.w * v.w;
    block_reduce2(s1, s2);
    float mu = s1 * (1.f / EE);
    float var = s2 * (1.f / EE) - mu * mu;
    float rs = rsqrtf(var + 1e-5f);
    float4 gg = *(const float4*)(g + c);
    float4 bb = *(const float4*)(bta + c);
    float4 o;
    o.x = (v.x - mu) * rs * gg.x + bb.x;
    o.y = (v.y - mu) * rs * gg.y + bb.y;
    o.z = (v.z - mu) * rs * gg.z + bb.z;
    o.w = (v.w - mu) * rs * gg.w + bb.w;
    *(float4*)(out + row * EE + c) = o;
}

__global__ __launch_bounds__(256) void newmem_kernel(
    const float* __restrict__ gmemM,
    const float* __restrict__ gupd,
    const float* __restrict__ upd,
    const float* __restrict__ memv,
    const float* __restrict__ wg, const float* __restrict__ wb,
    float* __restrict__ out)
{
    int row = blockIdx.x;
    int b = row >> 9, m = row & 511;
    int c = threadIdx.x * 4;
    float4 gm = *(const float4*)(gmemM + (size_t)m * EE + c);
    float4 gu = *(const float4*)(gupd + (size_t)b * EE + c);
    float4 uv = *(const float4*)(upd + (size_t)b * EE + c);
    float4 mv = *(const float4*)(memv + (size_t)m * EE + c);
    float ge[4] = {gm.x + gu.x, gm.y + gu.y, gm.z + gu.z, gm.w + gu.w};
    float u[4] = {uv.x, uv.y, uv.z, uv.w};
    float mmv[4] = {mv.x, mv.y, mv.z, mv.w};
    float x[4];
    float s1 = 0.f, s2 = 0.f;
#pragma unroll
    for (int i = 0; i < 4; i++) {
        float gt = 1.f / (1.f + __expf(-ge[i]));
        x[i] = gt * u[i] + (1.f - gt) * mmv[i];
        s1 += x[i]; s2 += x[i] * x[i];
    }
    block_reduce2(s1, s2);
    float mu = s1 * (1.f / EE);
    float var = s2 * (1.f / EE) - mu * mu;
    float rs = rsqrtf(var + 1e-5f);
    float4 gg = *(const float4*)(wg + c);
    float4 bb = *(const float4*)(wb + c);
    float4 o;
    o.x = (x[0] - mu) * rs * gg.x + bb.x;
    o.y = (x[1] - mu) * rs * gg.y + bb.y;
    o.z = (x[2] - mu) * rs * gg.z + bb.z;
    o.w = (x[3] - mu) * rs * gg.w + bb.w;
    *(float4*)(out + (size_t)row * EE + c) = o;
}

__global__ __launch_bounds__(256) void mean_kernel(
    const float* __restrict__ q, float* __restrict__ wq)
{
    __shared__ float red[8][33];
    int b = blockIdx.y;
    int e0 = blockIdx.x * 32;
    int el = threadIdx.x & 31, strip = threadIdx.x >> 5;
    const float* p = q + ((size_t)b * SS + strip * 256) * EE + e0 + el;
    float s = 0.f;
#pragma unroll 4
    for (int i = 0; i < 256; i++) s += p[(size_t)i * EE];
    red[strip][el] = s;
    __syncthreads();
    if (strip == 0) {
        float t = 0.f;
#pragma unroll
        for (int k = 0; k < 8; k++) t += red[k][el];
        wq[(size_t)b * EE + e0 + el] = t * (1.f / SS);
    }
}

__global__ __launch_bounds__(256) void gemv8(
    const float* __restrict__ A,
    const float* __restrict__ B, int ldb,
    const float* __restrict__ bias,
    float* __restrict__ C, int N, int K)
{
    int w = threadIdx.x >> 5, lane = threadIdx.x & 31;
    int n = blockIdx.x * 8 + w;
    if (n >= N) return;
    const float* brow = B + (size_t)n * ldb;
    for (int b = 0; b < BB; b++) {
        const float* arow = A + (size_t)b * K;
        float s = 0.f;
        for (int i = lane; i < K; i += 32) s += arow[i] * brow[i];
#pragma unroll
        for (int off = 16; off; off >>= 1) s += __shfl_xor_sync(0xffffffffu, s, off);
        if (lane == 0) C[(size_t)b * N + n] = s + (bias ? bias[n] : 0.f);
    }
}

// ---------------------------------------------------------------------------
extern "C" void kernel_launch(void* const* d_in, const int* in_sizes, int n_in,
                              void* d_out, int out_size)
{
    (void)in_sizes; (void)n_in; (void)out_size;
    const float* query   = (const float*)d_in[0];
    const float* memory  = (const float*)d_in[1];
    const float* r_in_w  = (const float*)d_in[2];
    const float* r_in_b  = (const float*)d_in[3];
    const float* r_out_w = (const float*)d_in[4];
    const float* r_out_b = (const float*)d_in[5];
    const float* w_in_w  = (const float*)d_in[6];
    const float* w_in_b  = (const float*)d_in[7];
    const float* w_out_w = (const float*)d_in[8];
    const float* w_out_b = (const float*)d_in[9];
    const float* rn_g    = (const float*)d_in[10];
    const float* rn_b    = (const float*)d_in[11];
    const float* wn_g    = (const float*)d_in[12];
    const float* wn_b    = (const float*)d_in[13];
    const float* gate_w  = (const float*)d_in[14];
    const float* gate_b  = (const float*)d_in[15];
    float* out = (float*)d_out;

    float *KV, *y, *wq, *vw, *upd, *gmem, *gupd;
    cudaGetSymbolAddress((void**)&KV,   g_KV);
    cudaGetSymbolAddress((void**)&y,    g_y);
    cudaGetSymbolAddress((void**)&wq,   g_wq);
    cudaGetSymbolAddress((void**)&vw,   g_vw);
    cudaGetSymbolAddress((void**)&upd,  g_upd);
    cudaGetSymbolAddress((void**)&gmem, g_gmem);
    cudaGetSymbolAddress((void**)&gupd, g_gupd);

    __nv_bfloat16 *qh, *ql, *qph, *qpl, *ahp, *alp, *mh, *ml, *kh, *kl, *vth, *vtl;
    __nv_bfloat16 *riwh, *riwl, *rowh, *rowl, *gwh, *gwl;
    cudaGetSymbolAddress((void**)&qh,   g_qh);
    cudaGetSymbolAddress((void**)&ql,   g_ql);
    cudaGetSymbolAddress((void**)&qph,  g_qph);
    cudaGetSymbolAddress((void**)&qpl,  g_qpl);
    cudaGetSymbolAddress((void**)&ahp,  g_ah);
    cudaGetSymbolAddress((void**)&alp,  g_al);
    cudaGetSymbolAddress((void**)&mh,   g_mh);
    cudaGetSymbolAddress((void**)&ml,   g_ml);
    cudaGetSymbolAddress((void**)&kh,   g_kh);
    cudaGetSymbolAddress((void**)&kl,   g_kl);
    cudaGetSymbolAddress((void**)&vth,  g_vth);
    cudaGetSymbolAddress((void**)&vtl,  g_vtl);
    cudaGetSymbolAddress((void**)&riwh, g_riwh);
    cudaGetSymbolAddress((void**)&riwl, g_riwl);
    cudaGetSymbolAddress((void**)&rowh, g_rowh);
    cudaGetSymbolAddress((void**)&rowl, g_rowl);
    cudaGetSymbolAddress((void**)&gwh,  g_gwh);
    cudaGetSymbolAddress((void**)&gwl,  g_gwl);

    cudaFuncSetAttribute(gemm_mma, cudaFuncAttributeMaxDynamicSharedMemorySize, GSMEM);
    cudaFuncSetAttribute(attn_mma, cudaFuncAttributeMaxDynamicSharedMemorySize, AT_SMEM);

    // --- split conversions (inputs + weights) ---
    cvt_split<<<3 * EE * EE / 1024, 256>>>(r_in_w, riwh, riwl, 3 * EE * EE);
    cvt_split<<<EE * EE / 1024, 256>>>(r_out_w, rowh, rowl, EE * EE);
    cvt_split<<<2 * EE * EE / 1024, 256>>>(gate_w, gwh, gwl, 2 * EE * EE);
    cvt_split<<<MM * EE / 1024, 256>>>(memory, mh, ml, MM * EE);
    cvt_split<<<BB * SS * EE / 1024, 256>>>(query, qh, ql, BB * SS * EE);

    // --- r-branch ---
    gemm_mma<<<dim3(2 * EE / 128, MM / 128), 256, GSMEM>>>(
        mh, ml, EE, riwh + (size_t)EE * EE, riwl + (size_t)EE * EE, EE,
        r_in_b + EE, nullptr, KV, nullptr, nullptr, 2 * EE, 1.f);
    split_k<<<MM, 256>>>(KV, kh, kl);
    transpose_v<<<dim3(EE / 32, MM / 32), 256>>>(KV, vth, vtl);
    gemm_mma<<<dim3(EE / 128, BB * SS / 128), 256, GSMEM>>>(
        qh, ql, EE, riwh, riwl, EE,
        r_in_b, nullptr, nullptr, qph, qpl, EE, 0.125f);
    attn_mma<<<dim3(SS / 128, HH, BB), 256, AT_SMEM>>>(
        qph, qpl, kh, kl, vth, vtl, ahp, alp);
    gemm_mma<<<dim3(EE / 128, BB * SS / 128), 256, GSMEM>>>(
        ahp, alp, EE, rowh, rowl, EE,
        r_out_b, query, y, nullptr, nullptr, EE, 1.f);
    ln_kernel<<<BB * SS, 256>>>(y, rn_g, rn_b, out);

    // --- w-branch (collapsed) ---
    mean_kernel<<<dim3(EE / 32, BB), 256>>>(query, wq);
    gemv8<<<EE / 8, 256>>>(wq, w_in_w + (size_t)2 * EE * EE, EE, w_in_b + 2 * EE, vw, EE, EE);
    gemv8<<<EE / 8, 256>>>(vw, w_out_w, EE, w_out_b, upd, EE, EE);

    // --- gate (decomposed) ---
    gemm_mma<<<dim3(EE / 128, MM / 128), 256, GSMEM>>>(
        mh, ml, EE, gwh, gwl, 2 * EE,
        gate_b, nullptr, gmem, nullptr, nullptr, EE, 1.f);
    gemv8<<<EE / 8, 256>>>(upd, gate_w + EE, 2 * EE, nullptr, gupd, EE, EE);

    newmem_kernel<<<BB * MM, 256>>>(gmem, gupd, upd, memory, wn_g, wn_b,
                                    out + (size_t)BB * SS * EE);
}